// round 8
// baseline (speedup 1.0000x reference)
#include <cuda_runtime.h>
#include <cuda_bf16.h>
#include <math.h>
#include <stdint.h>

#define S_LEN 2048
#define HID   2048
#define NH    16
#define NKV   4
#define HD    128
#define KVH   512

typedef __nv_bfloat16 bf16;

// ---------------- int8 split planes + scales (GEMM operands) ----------------
__device__ int8_t g_x0[S_LEN * HID],  g_x1[S_LEN * HID];
__device__ int8_t g_wq0[HID * HID],   g_wq1[HID * HID];
__device__ int8_t g_wk0[KVH * HID],   g_wk1[KVH * HID];
__device__ int8_t g_wv0[KVH * HID],   g_wv1[KVH * HID];
__device__ int8_t g_wo0[HID * HID],   g_wo1[HID * HID];
__device__ int8_t g_oq0[S_LEN * HID], g_oq1[S_LEN * HID];
__device__ float  g_sx[S_LEN], g_swq[HID], g_swk[KVH], g_swv[KVH], g_swo[HID], g_so[S_LEN];

// ---------------- bf16 split planes (flash operands) ----------------
__device__ bf16 g_qh[S_LEN * HID], g_ql[S_LEN * HID];
__device__ bf16 g_kh[S_LEN * KVH], g_kl[S_LEN * KVH];
__device__ bf16 g_vh[S_LEN * KVH], g_vl[S_LEN * KVH];
__device__ bf16 g_oh[S_LEN * HID], g_ol[S_LEN * HID];

__device__ __forceinline__ uint32_t smem_u32(const void* p) {
    return (uint32_t)__cvta_generic_to_shared(p);
}

#define MMA_BF16(c, a0, a1, a2, a3, b0, b1)                                 \
    asm("mma.sync.aligned.m16n8k16.row.col.f32.bf16.bf16.f32 "              \
        "{%0,%1,%2,%3},{%4,%5,%6,%7},{%8,%9},{%0,%1,%2,%3};"                \
        : "+f"(c[0]), "+f"(c[1]), "+f"(c[2]), "+f"(c[3])                    \
        : "r"(a0), "r"(a1), "r"(a2), "r"(a3), "r"(b0), "r"(b1))

#define MMA_S8(c, a, b0_, b1_)                                              \
    asm("mma.sync.aligned.m16n8k32.row.col.s32.s8.s8.s32 "                  \
        "{%0,%1,%2,%3},{%4,%5,%6,%7},{%8,%9},{%0,%1,%2,%3};"                \
        : "+r"((c)[0]), "+r"((c)[1]), "+r"((c)[2]), "+r"((c)[3])            \
        : "r"((a)[0]), "r"((a)[1]), "r"((a)[2]), "r"((a)[3]),               \
          "r"(b0_), "r"(b1_))

#define LDSM_X4(r0, r1, r2, r3, addr)                                       \
    asm("ldmatrix.sync.aligned.m8n8.x4.shared.b16 {%0,%1,%2,%3},[%4];"      \
        : "=r"(r0), "=r"(r1), "=r"(r2), "=r"(r3) : "r"(addr))

#define LDSM_X2(r0, r1, addr)                                               \
    asm("ldmatrix.sync.aligned.m8n8.x2.shared.b16 {%0,%1},[%2];"            \
        : "=r"(r0), "=r"(r1) : "r"(addr))

#define LDSM_X2T(r0, r1, addr)                                              \
    asm("ldmatrix.sync.aligned.m8n8.x2.trans.shared.b16 {%0,%1},[%2];"      \
        : "=r"(r0), "=r"(r1) : "r"(addr))

#define CP_ASYNC16(dst, src)                                                \
    asm volatile("cp.async.cg.shared.global [%0],[%1],16;"                  \
                 :: "r"(dst), "l"(src))
#define CP_COMMIT  asm volatile("cp.async.commit_group;" ::: "memory")
#define CP_WAIT(n) asm volatile("cp.async.wait_group %0;" :: "n"(n) : "memory")

__device__ __forceinline__ uint32_t pack2_hi(float x, float y) {
    __nv_bfloat162 t;
    t.x = __float2bfloat16(x); t.y = __float2bfloat16(y);
    return *(uint32_t*)&t;
}
__device__ __forceinline__ uint32_t pack2_lo(float x, float y) {
    __nv_bfloat162 t;
    t.x = __float2bfloat16(x - __bfloat162float(__float2bfloat16(x)));
    t.y = __float2bfloat16(y - __bfloat162float(__float2bfloat16(y)));
    return *(uint32_t*)&t;
}

// ---------------------------------------------------------------------------
// Row quantizer: x[row] -> s*(127*q0 + q1), s stored per row.
// src fp32 OR (srch+srcl) bf16 planes. One block per row, 256 threads, K=2048.
// ---------------------------------------------------------------------------
__global__ __launch_bounds__(256) void quant_rows(
    const float* __restrict__ src,
    const bf16* __restrict__ srch, const bf16* __restrict__ srcl,
    int8_t* __restrict__ q0, int8_t* __restrict__ q1,
    float* __restrict__ scale, int K)
{
    __shared__ float red[8];
    const int row = blockIdx.x, tid = threadIdx.x;
    const size_t base = (size_t)row * K;

    float v[8], mx = 0.f;
#pragma unroll
    for (int j = 0; j < 8; j++) {
        const int i = tid + j * 256;
        v[j] = src ? src[base + i]
                   : __bfloat162float(srch[base + i]) + __bfloat162float(srcl[base + i]);
        mx = fmaxf(mx, fabsf(v[j]));
    }
#pragma unroll
    for (int o = 16; o > 0; o >>= 1)
        mx = fmaxf(mx, __shfl_xor_sync(0xffffffffu, mx, o));
    if ((tid & 31) == 0) red[tid >> 5] = mx;
    __syncthreads();
    mx = fmaxf(fmaxf(fmaxf(red[0], red[1]), fmaxf(red[2], red[3])),
               fmaxf(fmaxf(red[4], red[5]), fmaxf(red[6], red[7])));
    const float inv = (mx > 0.f) ? 16129.f / mx : 0.f;
    if (tid == 0) scale[row] = (mx > 0.f) ? mx / 16129.f : 0.f;

#pragma unroll
    for (int j = 0; j < 8; j++) {
        const int i = tid + j * 256;
        float t  = v[j] * inv;
        float h  = rintf(t * (1.f / 127.f));
        float l  = rintf(t - 127.f * h);
        q0[base + i] = (int8_t)(int)h;
        q1[base + i] = (int8_t)(int)l;
    }
}

// ---------------------------------------------------------------------------
// int8 split GEMM: C[M,N] = A @ B^T (+bias). 128x128 tile, BK=64 bytes,
// double-buffered cp.async, 512 threads (16 warps, warp tile 32x32).
// 3 s8 MMAs per k32: acc0 += a0b0 ; acc1 += a0b1 + a1b0.
// value = sa*sb*(16129*acc0 + 127*acc1).
// ---------------------------------------------------------------------------
#define IPLANE_B 10240        // 128 rows * 80B (64 data + 16 pad)
#define IBUF_B   40960        // 4 planes
#define IGSMEM   81920        // 2 stages

__device__ __forceinline__ void i8_prefetch(
    uint32_t s_base, int buf,
    const int8_t* __restrict__ A0, const int8_t* __restrict__ A1,
    const int8_t* __restrict__ B0, const int8_t* __restrict__ B1,
    int bm, int bn, int K, int k0, int tid)
{
    const int row = tid >> 2, seg = (tid & 3) * 16;
    const uint32_t dst0 = s_base + (uint32_t)buf * IBUF_B + (uint32_t)(row * 80 + seg);
    const size_t offA = (size_t)(bm + row) * K + k0 + seg;
    const size_t offB = (size_t)(bn + row) * K + k0 + seg;
    CP_ASYNC16(dst0,                A0 + offA);
    CP_ASYNC16(dst0 + IPLANE_B,     A1 + offA);
    CP_ASYNC16(dst0 + 2 * IPLANE_B, B0 + offB);
    CP_ASYNC16(dst0 + 3 * IPLANE_B, B1 + offB);
}

__device__ __forceinline__ void gemm_i8_core(
    const int8_t* __restrict__ A0, const int8_t* __restrict__ A1,
    const float* __restrict__ sa,
    const int8_t* __restrict__ B0, const int8_t* __restrict__ B1,
    const float* __restrict__ sb, const float* __restrict__ bias,
    bf16* __restrict__ Ch, bf16* __restrict__ Cl, float* __restrict__ Cf,
    int bm, int bn, int N, int K)
{
    extern __shared__ char ismem[];
    const uint32_t s_base = smem_u32(ismem);
    const int tid  = threadIdx.x, warp = tid >> 5, lane = tid & 31;
    const int wm   = (warp & 3) * 32, wn = (warp >> 2) * 32;
    const int g    = lane >> 2, t2 = (lane & 3) * 2;
    const int arow = (lane & 7) + ((lane & 8) ? 8 : 0);
    const int hi16A = (lane & 16) ? 16 : 0;
    const int brow = lane & 7;
    const int hi16B = (lane & 8) ? 16 : 0;

    int acc0[2][4][4], acc1[2][4][4];
#pragma unroll
    for (int mi = 0; mi < 2; mi++)
#pragma unroll
        for (int ni = 0; ni < 4; ni++)
#pragma unroll
            for (int q = 0; q < 4; q++) { acc0[mi][ni][q] = 0; acc1[mi][ni][q] = 0; }

    const int nchunk = K >> 6;
    i8_prefetch(s_base, 0, A0, A1, B0, B1, bm, bn, K, 0, tid);
    CP_COMMIT;

    for (int c = 0; c < nchunk; c++) {
        if (c + 1 < nchunk) {
            i8_prefetch(s_base, (c + 1) & 1, A0, A1, B0, B1, bm, bn, K, (c + 1) << 6, tid);
            CP_COMMIT;
            CP_WAIT(1);
        } else {
            CP_WAIT(0);
        }
        __syncthreads();

        const uint32_t bufb = s_base + (uint32_t)(c & 1) * IBUF_B;
#pragma unroll
        for (int ks = 0; ks < 2; ks++) {
            uint32_t a0f[2][4], a1f[2][4], b0f[4][2], b1f[4][2];
#pragma unroll
            for (int mi = 0; mi < 2; mi++) {
                const uint32_t ad = bufb + (uint32_t)((wm + mi * 16 + arow) * 80 + ks * 32 + hi16A);
                LDSM_X4(a0f[mi][0], a0f[mi][1], a0f[mi][2], a0f[mi][3], ad);
                LDSM_X4(a1f[mi][0], a1f[mi][1], a1f[mi][2], a1f[mi][3], ad + IPLANE_B);
            }
#pragma unroll
            for (int ni = 0; ni < 4; ni++) {
                const uint32_t bd = bufb + 2 * IPLANE_B
                                  + (uint32_t)((wn + ni * 8 + brow) * 80 + ks * 32 + hi16B);
                LDSM_X2(b0f[ni][0], b0f[ni][1], bd);
                LDSM_X2(b1f[ni][0], b1f[ni][1], bd + IPLANE_B);
            }
#pragma unroll
            for (int mi = 0; mi < 2; mi++)
#pragma unroll
                for (int ni = 0; ni < 4; ni++) {
                    MMA_S8(acc0[mi][ni], a0f[mi], b0f[ni][0], b0f[ni][1]);
                    MMA_S8(acc1[mi][ni], a0f[mi], b1f[ni][0], b1f[ni][1]);
                    MMA_S8(acc1[mi][ni], a1f[mi], b0f[ni][0], b0f[ni][1]);
                }
        }
        __syncthreads();
    }

#pragma unroll
    for (int mi = 0; mi < 2; mi++) {
        const int row0 = bm + wm + mi * 16 + g;
        const float sa0 = sa[row0], sa1 = sa[row0 + 8];
#pragma unroll
        for (int ni = 0; ni < 4; ni++) {
            const int col = bn + wn + ni * 8 + t2;
            const float sb0 = sb[col], sb1 = sb[col + 1];
            const float bb0 = bias ? bias[col] : 0.f;
            const float bb1 = bias ? bias[col + 1] : 0.f;
            float v0 = sa0 * sb0 * (16129.f * (float)acc0[mi][ni][0] + 127.f * (float)acc1[mi][ni][0]) + bb0;
            float v1 = sa0 * sb1 * (16129.f * (float)acc0[mi][ni][1] + 127.f * (float)acc1[mi][ni][1]) + bb1;
            float v2 = sa1 * sb0 * (16129.f * (float)acc0[mi][ni][2] + 127.f * (float)acc1[mi][ni][2]) + bb0;
            float v3 = sa1 * sb1 * (16129.f * (float)acc0[mi][ni][3] + 127.f * (float)acc1[mi][ni][3]) + bb1;
            if (Cf) {
                float2 w0; w0.x = v0; w0.y = v1;
                float2 w1; w1.x = v2; w1.y = v3;
                *(float2*)&Cf[(size_t)row0 * N + col]       = w0;
                *(float2*)&Cf[(size_t)(row0 + 8) * N + col] = w1;
            } else {
                *(uint32_t*)&Ch[(size_t)row0 * N + col]       = pack2_hi(v0, v1);
                *(uint32_t*)&Cl[(size_t)row0 * N + col]       = pack2_lo(v0, v1);
                *(uint32_t*)&Ch[(size_t)(row0 + 8) * N + col] = pack2_hi(v2, v3);
                *(uint32_t*)&Cl[(size_t)(row0 + 8) * N + col] = pack2_lo(v2, v3);
            }
        }
    }
}

// Fused QKV: blockIdx.x 0..15 -> Q, 16..19 -> K, 20..23 -> V
__global__ __launch_bounds__(512) void qkv_i8(
    const float* __restrict__ bq, const float* __restrict__ bk,
    const float* __restrict__ bv)
{
    const int bx = blockIdx.x, bm = blockIdx.y * 128;
    if (bx < 16)
        gemm_i8_core(g_x0, g_x1, g_sx, g_wq0, g_wq1, g_swq, bq,
                     g_qh, g_ql, nullptr, bm, bx * 128, HID, HID);
    else if (bx < 20)
        gemm_i8_core(g_x0, g_x1, g_sx, g_wk0, g_wk1, g_swk, bk,
                     g_kh, g_kl, nullptr, bm, (bx - 16) * 128, KVH, HID);
    else
        gemm_i8_core(g_x0, g_x1, g_sx, g_wv0, g_wv1, g_swv, bv,
                     g_vh, g_vl, nullptr, bm, (bx - 20) * 128, KVH, HID);
}

__global__ __launch_bounds__(512) void o_i8(float* __restrict__ out)
{
    gemm_i8_core(g_oq0, g_oq1, g_so, g_wo0, g_wo1, g_swo, nullptr,
                 nullptr, nullptr, out, blockIdx.y * 128, blockIdx.x * 128, HID, HID);
}

// ---------------------------------------------------------------------------
// RoPE in-place on bf16 split planes (position_ids are int32)
// ---------------------------------------------------------------------------
__global__ void rope_sp(bf16* __restrict__ hi, bf16* __restrict__ lo,
                        const int* __restrict__ pos_ids,
                        int nheads, int stride, int total)
{
    int idx = blockIdx.x * blockDim.x + threadIdx.x;
    if (idx >= total) return;
    int i = idx & 63;
    int h = (idx >> 6) % nheads;
    int s = idx / (64 * nheads);

    float pos = (float)pos_ids[s];
    float inv = expf(-(float)(2 * i) * (1.0f / 128.0f) * 9.210340371976184f);
    float ang = pos * inv;
    float c, sn;
    sincosf(ang, &sn, &c);

    size_t base = (size_t)s * stride + h * HD;
    float x0 = __bfloat162float(hi[base + i])      + __bfloat162float(lo[base + i]);
    float x1 = __bfloat162float(hi[base + i + 64]) + __bfloat162float(lo[base + i + 64]);
    float y0 = x0 * c - x1 * sn;
    float y1 = x1 * c + x0 * sn;
    bf16 h0 = __float2bfloat16(y0);
    bf16 h1 = __float2bfloat16(y1);
    hi[base + i]      = h0;
    lo[base + i]      = __float2bfloat16(y0 - __bfloat162float(h0));
    hi[base + i + 64] = h1;
    lo[base + i + 64] = __float2bfloat16(y1 - __bfloat162float(h1));
}

// ---------------------------------------------------------------------------
// Flash attention, warp-mma bf16 3-term, split planes in/out. Causal, GQA 4:1.
// ---------------------------------------------------------------------------
#define FLQ 136
#define FSMEM ((2 * 128 * FLQ + 4 * 64 * FLQ) * 2)

__global__ __launch_bounds__(256) void flash_sp()
{
    extern __shared__ bf16 sm[];
    bf16* Qh = sm;
    bf16* Ql = Qh + 128 * FLQ;
    bf16* Kh = Ql + 128 * FLQ;
    bf16* Kl = Kh + 64 * FLQ;
    bf16* Vh = Kl + 64 * FLQ;
    bf16* Vl = Vh + 64 * FLQ;
    const uint32_t aQh = smem_u32(Qh), aQl = smem_u32(Ql);
    const uint32_t aKh = smem_u32(Kh), aKl = smem_u32(Kl);
    const uint32_t aVh = smem_u32(Vh), aVl = smem_u32(Vl);

    const int h   = blockIdx.y;
    const int qt  = blockIdx.x;
    const int q0  = qt * 128;
    const int kvh = h >> 2;
    const int tid = threadIdx.x, warp = tid >> 5, lane = tid & 31;
    const int g   = lane >> 2, t2 = (lane & 3) * 2;

#pragma unroll
    for (int j = 0; j < 16; j++) {
        const int plane = j >> 3;
        const int t = tid * 8 + (j & 7);
        const int r = t >> 4, c16 = t & 15;
        const bf16* src = (plane ? g_ql : g_qh) + (size_t)(q0 + r) * HID + h * HD + c16 * 8;
        uint32_t dst = (plane ? aQl : aQh) + (uint32_t)(r * FLQ + c16 * 8) * 2;
        CP_ASYNC16(dst, src);
    }
    CP_COMMIT;

    float m0 = -1e30f, m1 = -1e30f, l0 = 0.f, l1 = 0.f;
    float oacc[16][4];
#pragma unroll
    for (int nf = 0; nf < 16; nf++)
#pragma unroll
        for (int q = 0; q < 4; q++) oacc[nf][q] = 0.f;

    const float scale = 0.08838834764831845f;
    const int mrow = warp * 16;
    const int r0 = q0 + mrow + g, r1 = r0 + 8;
    const int wmax = q0 + mrow + 15;
    const int arow = (lane & 7) + ((lane & 8) ? 8 : 0);
    const int brow = lane & 7;
    const int vrow = lane & 15;

    const int ntiles = 2 * qt + 2;
    for (int t = 0; t < ntiles; t++) {
        const int j0 = t * 64;
        __syncthreads();
#pragma unroll
        for (int j = 0; j < 16; j++) {
            const int plane = j >> 2;
            const int tt = tid * 4 + (j & 3);
            const int r = tt >> 4, c16 = tt & 15;
            const bf16* src;
            uint32_t dstb;
            if (plane == 0)      { src = g_kh; dstb = aKh; }
            else if (plane == 1) { src = g_kl; dstb = aKl; }
            else if (plane == 2) { src = g_vh; dstb = aVh; }
            else                 { src = g_vl; dstb = aVl; }
            src += (size_t)(j0 + r) * KVH + kvh * HD + c16 * 8;
            CP_ASYNC16(dstb + (uint32_t)(r * FLQ + c16 * 8) * 2, src);
        }
        CP_COMMIT;
        CP_WAIT(0);
        __syncthreads();
        if (j0 > wmax) continue;

        float s[8][4];
#pragma unroll
        for (int nf = 0; nf < 8; nf++)
#pragma unroll
            for (int q = 0; q < 4; q++) s[nf][q] = 0.f;

#pragma unroll
        for (int kt = 0; kt < 128; kt += 16) {
            const int acol = kt + ((lane & 16) ? 8 : 0);
            uint32_t qh[4], ql[4];
            LDSM_X4(qh[0], qh[1], qh[2], qh[3], smem_u32(&Qh[(mrow + arow) * FLQ + acol]));
            LDSM_X4(ql[0], ql[1], ql[2], ql[3], smem_u32(&Ql[(mrow + arow) * FLQ + acol]));
            const int bcol = kt + ((lane & 8) ? 8 : 0);
#pragma unroll
            for (int nf = 0; nf < 8; nf++) {
                uint32_t bh0, bh1, bl0, bl1;
                LDSM_X2(bh0, bh1, smem_u32(&Kh[(nf * 8 + brow) * FLQ + bcol]));
                LDSM_X2(bl0, bl1, smem_u32(&Kl[(nf * 8 + brow) * FLQ + bcol]));
                MMA_BF16(s[nf], qh[0], qh[1], qh[2], qh[3], bh0, bh1);
                MMA_BF16(s[nf], qh[0], qh[1], qh[2], qh[3], bl0, bl1);
                MMA_BF16(s[nf], ql[0], ql[1], ql[2], ql[3], bh0, bh1);
            }
        }

#pragma unroll
        for (int nf = 0; nf < 8; nf++)
#pragma unroll
            for (int q = 0; q < 4; q++) s[nf][q] *= scale;

        if (j0 + 63 > r0) {
#pragma unroll
            for (int nf = 0; nf < 8; nf++) {
                const int c0 = j0 + nf * 8 + t2;
                if (c0     > r0) s[nf][0] = -1e30f;
                if (c0 + 1 > r0) s[nf][1] = -1e30f;
                if (c0     > r1) s[nf][2] = -1e30f;
                if (c0 + 1 > r1) s[nf][3] = -1e30f;
            }
        }

        float mx0 = -1e30f, mx1 = -1e30f;
#pragma unroll
        for (int nf = 0; nf < 8; nf++) {
            mx0 = fmaxf(mx0, fmaxf(s[nf][0], s[nf][1]));
            mx1 = fmaxf(mx1, fmaxf(s[nf][2], s[nf][3]));
        }
        mx0 = fmaxf(mx0, __shfl_xor_sync(0xffffffffu, mx0, 1));
        mx0 = fmaxf(mx0, __shfl_xor_sync(0xffffffffu, mx0, 2));
        mx1 = fmaxf(mx1, __shfl_xor_sync(0xffffffffu, mx1, 1));
        mx1 = fmaxf(mx1, __shfl_xor_sync(0xffffffffu, mx1, 2));
        const float mn0 = fmaxf(m0, mx0), mn1 = fmaxf(m1, mx1);
        const float a0 = __expf(m0 - mn0), a1 = __expf(m1 - mn1);
        float sum0 = 0.f, sum1 = 0.f;
#pragma unroll
        for (int nf = 0; nf < 8; nf++) {
            s[nf][0] = __expf(s[nf][0] - mn0);
            s[nf][1] = __expf(s[nf][1] - mn0);
            s[nf][2] = __expf(s[nf][2] - mn1);
            s[nf][3] = __expf(s[nf][3] - mn1);
            sum0 += s[nf][0] + s[nf][1];
            sum1 += s[nf][2] + s[nf][3];
        }
        sum0 += __shfl_xor_sync(0xffffffffu, sum0, 1);
        sum0 += __shfl_xor_sync(0xffffffffu, sum0, 2);
        sum1 += __shfl_xor_sync(0xffffffffu, sum1, 1);
        sum1 += __shfl_xor_sync(0xffffffffu, sum1, 2);
        l0 = l0 * a0 + sum0;  l1 = l1 * a1 + sum1;
        m0 = mn0;             m1 = mn1;
#pragma unroll
        for (int nf = 0; nf < 16; nf++) {
            oacc[nf][0] *= a0; oacc[nf][1] *= a0;
            oacc[nf][2] *= a1; oacc[nf][3] *= a1;
        }

        uint32_t pah[4][4], pal[4][4];
#pragma unroll
        for (int j = 0; j < 4; j++) {
            pah[j][0] = pack2_hi(s[2*j][0],   s[2*j][1]);
            pah[j][1] = pack2_hi(s[2*j][2],   s[2*j][3]);
            pah[j][2] = pack2_hi(s[2*j+1][0], s[2*j+1][1]);
            pah[j][3] = pack2_hi(s[2*j+1][2], s[2*j+1][3]);
            pal[j][0] = pack2_lo(s[2*j][0],   s[2*j][1]);
            pal[j][1] = pack2_lo(s[2*j][2],   s[2*j][3]);
            pal[j][2] = pack2_lo(s[2*j+1][0], s[2*j+1][1]);
            pal[j][3] = pack2_lo(s[2*j+1][2], s[2*j+1][3]);
        }

#pragma unroll
        for (int j = 0; j < 4; j++) {
#pragma unroll
            for (int nf = 0; nf < 16; nf++) {
                uint32_t bh0, bh1, bl0, bl1;
                LDSM_X2T(bh0, bh1, smem_u32(&Vh[(16 * j + vrow) * FLQ + nf * 8]));
                LDSM_X2T(bl0, bl1, smem_u32(&Vl[(16 * j + vrow) * FLQ + nf * 8]));
                MMA_BF16(oacc[nf], pah[j][0], pah[j][1], pah[j][2], pah[j][3], bh0, bh1);
                MMA_BF16(oacc[nf], pah[j][0], pah[j][1], pah[j][2], pah[j][3], bl0, bl1);
                MMA_BF16(oacc[nf], pal[j][0], pal[j][1], pal[j][2], pal[j][3], bh0, bh1);
            }
        }
    }

    const float inv0 = 1.f / l0, inv1 = 1.f / l1;
#pragma unroll
    for (int nf = 0; nf < 16; nf++) {
        const int col = h * HD + nf * 8 + t2;
        float v0 = oacc[nf][0] * inv0, v1 = oacc[nf][1] * inv0;
        float v2 = oacc[nf][2] * inv1, v3 = oacc[nf][3] * inv1;
        *(uint32_t*)&g_oh[(size_t)r0 * HID + col] = pack2_hi(v0, v1);
        *(uint32_t*)&g_ol[(size_t)r0 * HID + col] = pack2_lo(v0, v1);
        *(uint32_t*)&g_oh[(size_t)r1 * HID + col] = pack2_hi(v2, v3);
        *(uint32_t*)&g_ol[(size_t)r1 * HID + col] = pack2_lo(v2, v3);
    }
}

// ---------------------------------------------------------------------------

extern "C" void kernel_launch(void* const* d_in, const int* in_sizes, int n_in,
                              void* d_out, int out_size)
{
    const float* x   = (const float*)d_in[0];
    /* d_in[1] attention_mask: exact causal triu(-inf), applied analytically */
    const int*   pos = (const int*)d_in[2];
    const float* wq  = (const float*)d_in[3];
    const float* bq  = (const float*)d_in[4];
    const float* wk  = (const float*)d_in[5];
    const float* bk  = (const float*)d_in[6];
    const float* wv  = (const float*)d_in[7];
    const float* bv  = (const float*)d_in[8];
    const float* wo  = (const float*)d_in[9];
    float*       out = (float*)d_out;

    int8_t *x0, *x1, *wq0, *wq1, *wk0, *wk1, *wv0, *wv1, *wo0, *wo1, *oq0, *oq1;
    float *sx, *swq, *swk, *swv, *swo, *so;
    bf16 *qh, *ql, *kh, *kl, *oh, *ol;
    cudaGetSymbolAddress((void**)&x0,  g_x0);  cudaGetSymbolAddress((void**)&x1,  g_x1);
    cudaGetSymbolAddress((void**)&wq0, g_wq0); cudaGetSymbolAddress((void**)&wq1, g_wq1);
    cudaGetSymbolAddress((void**)&wk0, g_wk0); cudaGetSymbolAddress((void**)&wk1, g_wk1);
    cudaGetSymbolAddress((void**)&wv0, g_wv0); cudaGetSymbolAddress((void**)&wv1, g_wv1);
    cudaGetSymbolAddress((void**)&wo0, g_wo0); cudaGetSymbolAddress((void**)&wo1, g_wo1);
    cudaGetSymbolAddress((void**)&oq0, g_oq0); cudaGetSymbolAddress((void**)&oq1, g_oq1);
    cudaGetSymbolAddress((void**)&sx,  g_sx);  cudaGetSymbolAddress((void**)&swq, g_swq);
    cudaGetSymbolAddress((void**)&swk, g_swk); cudaGetSymbolAddress((void**)&swv, g_swv);
    cudaGetSymbolAddress((void**)&swo, g_swo); cudaGetSymbolAddress((void**)&so,  g_so);
    cudaGetSymbolAddress((void**)&qh,  g_qh);  cudaGetSymbolAddress((void**)&ql,  g_ql);
    cudaGetSymbolAddress((void**)&kh,  g_kh);  cudaGetSymbolAddress((void**)&kl,  g_kl);
    cudaGetSymbolAddress((void**)&oh,  g_oh);  cudaGetSymbolAddress((void**)&ol,  g_ol);

    cudaFuncSetAttribute(qkv_i8,   cudaFuncAttributeMaxDynamicSharedMemorySize, IGSMEM);
    cudaFuncSetAttribute(o_i8,     cudaFuncAttributeMaxDynamicSharedMemorySize, IGSMEM);
    cudaFuncSetAttribute(flash_sp, cudaFuncAttributeMaxDynamicSharedMemorySize, FSMEM);

    // quantize activations + weights (int8 split, per-row scale)
    quant_rows<<<S_LEN, 256>>>(x,  nullptr, nullptr, x0,  x1,  sx,  HID);
    quant_rows<<<HID,   256>>>(wq, nullptr, nullptr, wq0, wq1, swq, HID);
    quant_rows<<<KVH,   256>>>(wk, nullptr, nullptr, wk0, wk1, swk, HID);
    quant_rows<<<KVH,   256>>>(wv, nullptr, nullptr, wv0, wv1, swv, HID);
    quant_rows<<<HID,   256>>>(wo, nullptr, nullptr, wo0, wo1, swo, HID);

    // fused QKV projection (int8 tensor core)
    qkv_i8<<<dim3(24, 16), 512, IGSMEM>>>(bq, bk, bv);

    // RoPE on bf16 split planes
    {
        int totq = S_LEN * NH * 64;
        rope_sp<<<(totq + 255) / 256, 256>>>(qh, ql, pos, NH, HID, totq);
        int totk = S_LEN * NKV * 64;
        rope_sp<<<(totk + 255) / 256, 256>>>(kh, kl, pos, NKV, KVH, totk);
    }

    // flash attention (bf16 3-term)
    flash_sp<<<dim3(S_LEN / 128, NH), 256, FSMEM>>>();

    // quantize attention output, then output projection (int8) -> fp32
    quant_rows<<<S_LEN, 256>>>(nullptr, oh, ol, oq0, oq1, so, HID);
    o_i8<<<dim3(16, 16), 512, IGSMEM>>>(out);
}

// round 10
// speedup vs baseline: 2.8119x; 2.8119x over previous
#include <cuda_runtime.h>
#include <cuda_bf16.h>
#include <math.h>
#include <stdint.h>

#define S_LEN 2048
#define HID   2048
#define NH    16
#define NKV   4
#define HD    128
#define KVH   512

typedef __nv_bfloat16 bf16;

// ------------------- split-plane scratch (bf16 hi/lo) -------------------
__device__ bf16 g_xh[S_LEN * HID], g_xl[S_LEN * HID];
__device__ bf16 g_wqh[HID * HID],  g_wql[HID * HID];
__device__ bf16 g_wkh[KVH * HID],  g_wkl[KVH * HID];
__device__ bf16 g_wvh[KVH * HID],  g_wvl[KVH * HID];
__device__ bf16 g_woh[HID * HID],  g_wol[HID * HID];
__device__ bf16 g_qh[S_LEN * HID], g_ql[S_LEN * HID];
__device__ bf16 g_kh[S_LEN * KVH], g_kl[S_LEN * KVH];
__device__ bf16 g_vh[S_LEN * KVH], g_vl[S_LEN * KVH];
__device__ bf16 g_oh[S_LEN * HID], g_ol[S_LEN * HID];

__device__ __forceinline__ uint32_t smem_u32(const void* p) {
    return (uint32_t)__cvta_generic_to_shared(p);
}

#define MMA_BF16(c, a0, a1, a2, a3, b0, b1)                                 \
    asm("mma.sync.aligned.m16n8k16.row.col.f32.bf16.bf16.f32 "              \
        "{%0,%1,%2,%3},{%4,%5,%6,%7},{%8,%9},{%0,%1,%2,%3};"                \
        : "+f"(c[0]), "+f"(c[1]), "+f"(c[2]), "+f"(c[3])                    \
        : "r"(a0), "r"(a1), "r"(a2), "r"(a3), "r"(b0), "r"(b1))

#define LDSM_X4(r0, r1, r2, r3, addr)                                       \
    asm("ldmatrix.sync.aligned.m8n8.x4.shared.b16 {%0,%1,%2,%3},[%4];"      \
        : "=r"(r0), "=r"(r1), "=r"(r2), "=r"(r3) : "r"(addr))

#define LDSM_X2(r0, r1, addr)                                               \
    asm("ldmatrix.sync.aligned.m8n8.x2.shared.b16 {%0,%1},[%2];"            \
        : "=r"(r0), "=r"(r1) : "r"(addr))

#define LDSM_X2T(r0, r1, addr)                                              \
    asm("ldmatrix.sync.aligned.m8n8.x2.trans.shared.b16 {%0,%1},[%2];"      \
        : "=r"(r0), "=r"(r1) : "r"(addr))

#define CP_ASYNC16(dst, src)                                                \
    asm volatile("cp.async.cg.shared.global [%0],[%1],16;"                  \
                 :: "r"(dst), "l"(src))
#define CP_COMMIT  asm volatile("cp.async.commit_group;" ::: "memory")
#define CP_WAIT(n) asm volatile("cp.async.wait_group %0;" :: "n"(n) : "memory")

__device__ __forceinline__ uint32_t pack2_hi(float x, float y) {
    __nv_bfloat162 t;
    t.x = __float2bfloat16(x); t.y = __float2bfloat16(y);
    return *(uint32_t*)&t;
}
__device__ __forceinline__ uint32_t pack2_lo(float x, float y) {
    __nv_bfloat162 t;
    t.x = __float2bfloat16(x - __bfloat162float(__float2bfloat16(x)));
    t.y = __float2bfloat16(y - __bfloat162float(__float2bfloat16(y)));
    return *(uint32_t*)&t;
}

// ---------------------------------------------------------------------------
// f32 -> (hi, lo) bf16 plane split (one-shot, memory bound)
// ---------------------------------------------------------------------------
__global__ void split_f32(const float* __restrict__ in,
                          bf16* __restrict__ hi, bf16* __restrict__ lo, int n4)
{
    int i = blockIdx.x * blockDim.x + threadIdx.x;
    if (i >= n4) return;
    float4 v = ((const float4*)in)[i];
    ((uint32_t*)hi)[i * 2]     = pack2_hi(v.x, v.y);
    ((uint32_t*)hi)[i * 2 + 1] = pack2_hi(v.z, v.w);
    ((uint32_t*)lo)[i * 2]     = pack2_lo(v.x, v.y);
    ((uint32_t*)lo)[i * 2 + 1] = pack2_lo(v.z, v.w);
}

// ---------------------------------------------------------------------------
// GEMM core: C[M,N] = A @ B^T (+bias). bf16 planes in, 3-term MMA, term-major
// issue order. 128x128 tile, BK=32, double-buffered cp.async, 8 warps (2Mx4N).
// ---------------------------------------------------------------------------
#define PLANE_B 10240          // 128 rows * 40 elems * 2B
#define BUF_B   40960          // 4 planes
#define GSMEM   81920          // 2 buffers

__device__ __forceinline__ void gemm_prefetch(
    uint32_t s_base, int buf,
    const bf16* __restrict__ Ahg, const bf16* __restrict__ Alg,
    const bf16* __restrict__ Bhg, const bf16* __restrict__ Blg,
    int bm, int bn, int K, int k0, int tid)
{
#pragma unroll
    for (int j = 0; j < 8; j++) {
        const int plane = j >> 1;
        const int t = tid * 2 + (j & 1);     // 0..511
        const int r = t >> 2, c8 = t & 3;
        const bf16* src = (plane == 0) ? Ahg : (plane == 1) ? Alg
                        : (plane == 2) ? Bhg : Blg;
        const int rowbase = (plane < 2) ? bm : bn;
        uint32_t dst = s_base + (uint32_t)buf * BUF_B + (uint32_t)plane * PLANE_B
                     + (uint32_t)(r * 40 + c8 * 8) * 2;
        CP_ASYNC16(dst, src + (size_t)(rowbase + r) * K + k0 + c8 * 8);
    }
}

__device__ __forceinline__ void gemm_core(
    const bf16* __restrict__ Ahg, const bf16* __restrict__ Alg,
    const bf16* __restrict__ Bhg, const bf16* __restrict__ Blg,
    const float* __restrict__ bias,
    bf16* __restrict__ Ch, bf16* __restrict__ Cl, float* __restrict__ Cf,
    int bm, int bn, int N, int K)
{
    extern __shared__ bf16 smbuf[];
    const uint32_t s_base = smem_u32(smbuf);
    const int tid  = threadIdx.x, warp = tid >> 5, lane = tid & 31;
    const int wm   = (warp & 1) * 64, wn = (warp >> 1) * 32;
    const int g    = lane >> 2, t2 = (lane & 3) * 2;
    const int arow = (lane & 7) + ((lane & 8) ? 8 : 0);
    const int brow = lane & 7;

    float acc[4][4][4];
#pragma unroll
    for (int mi = 0; mi < 4; mi++)
#pragma unroll
        for (int ni = 0; ni < 4; ni++)
#pragma unroll
            for (int q = 0; q < 4; q++) acc[mi][ni][q] = 0.f;

    const int nchunk = K >> 5;
    gemm_prefetch(s_base, 0, Ahg, Alg, Bhg, Blg, bm, bn, K, 0, tid);
    CP_COMMIT;

    for (int c = 0; c < nchunk; c++) {
        if (c + 1 < nchunk) {
            gemm_prefetch(s_base, (c + 1) & 1, Ahg, Alg, Bhg, Blg,
                          bm, bn, K, (c + 1) << 5, tid);
            CP_COMMIT;
            CP_WAIT(1);
        } else {
            CP_WAIT(0);
        }
        __syncthreads();

        const uint32_t bufb = s_base + (uint32_t)(c & 1) * BUF_B;
        const uint32_t aAh = bufb, aAl = bufb + PLANE_B;
        const uint32_t aBh = bufb + 2 * PLANE_B, aBl = bufb + 3 * PLANE_B;

#pragma unroll
        for (int kt = 0; kt < 32; kt += 16) {
            const int acol = kt + ((lane & 16) ? 8 : 0);
            uint32_t ah[4][4], al[4][4];
#pragma unroll
            for (int mi = 0; mi < 4; mi++) {
                const uint32_t off = (uint32_t)((wm + mi * 16 + arow) * 40 + acol) * 2;
                LDSM_X4(ah[mi][0], ah[mi][1], ah[mi][2], ah[mi][3], aAh + off);
                LDSM_X4(al[mi][0], al[mi][1], al[mi][2], al[mi][3], aAl + off);
            }
            const int bcol = kt + ((lane & 8) ? 8 : 0);
#pragma unroll
            for (int ni = 0; ni < 4; ni++) {
                const uint32_t boff = (uint32_t)((wn + ni * 8 + brow) * 40 + bcol) * 2;
                uint32_t bh0, bh1, bl0, bl1;
                LDSM_X2(bh0, bh1, aBh + boff);
                LDSM_X2(bl0, bl1, aBl + boff);
                // term-major: 4 independent MMAs between same-acc reuses
#pragma unroll
                for (int mi = 0; mi < 4; mi++)
                    MMA_BF16(acc[mi][ni], ah[mi][0], ah[mi][1], ah[mi][2], ah[mi][3], bh0, bh1);
#pragma unroll
                for (int mi = 0; mi < 4; mi++)
                    MMA_BF16(acc[mi][ni], ah[mi][0], ah[mi][1], ah[mi][2], ah[mi][3], bl0, bl1);
#pragma unroll
                for (int mi = 0; mi < 4; mi++)
                    MMA_BF16(acc[mi][ni], al[mi][0], al[mi][1], al[mi][2], al[mi][3], bh0, bh1);
            }
        }
        __syncthreads();
    }

#pragma unroll
    for (int mi = 0; mi < 4; mi++) {
#pragma unroll
        for (int ni = 0; ni < 4; ni++) {
            const int row = bm + wm + mi * 16 + g;
            const int col = bn + wn + ni * 8 + t2;
            float b0 = bias ? bias[col] : 0.f;
            float b1 = bias ? bias[col + 1] : 0.f;
            float v0 = acc[mi][ni][0] + b0, v1 = acc[mi][ni][1] + b1;
            float v2 = acc[mi][ni][2] + b0, v3 = acc[mi][ni][3] + b1;
            if (Cf) {
                float2 w0; w0.x = v0; w0.y = v1;
                float2 w1; w1.x = v2; w1.y = v3;
                *(float2*)&Cf[(size_t)row * N + col]       = w0;
                *(float2*)&Cf[(size_t)(row + 8) * N + col] = w1;
            } else {
                *(uint32_t*)&Ch[(size_t)row * N + col]       = pack2_hi(v0, v1);
                *(uint32_t*)&Cl[(size_t)row * N + col]       = pack2_lo(v0, v1);
                *(uint32_t*)&Ch[(size_t)(row + 8) * N + col] = pack2_hi(v2, v3);
                *(uint32_t*)&Cl[(size_t)(row + 8) * N + col] = pack2_lo(v2, v3);
            }
        }
    }
}

// Fused QKV projection: blockIdx.x 0..15 -> Q, 16..19 -> K, 20..23 -> V
__global__ __launch_bounds__(256) void qkv_gemm(
    const float* __restrict__ bq, const float* __restrict__ bk,
    const float* __restrict__ bv)
{
    const int bx = blockIdx.x, bm = blockIdx.y * 128;
    const bf16 *Bh, *Bl; const float* bias; bf16 *Ch, *Cl; int N, bn;
    if (bx < 16)      { Bh = g_wqh; Bl = g_wql; bias = bq; Ch = g_qh; Cl = g_ql; N = HID; bn = bx * 128; }
    else if (bx < 20) { Bh = g_wkh; Bl = g_wkl; bias = bk; Ch = g_kh; Cl = g_kl; N = KVH; bn = (bx - 16) * 128; }
    else              { Bh = g_wvh; Bl = g_wvl; bias = bv; Ch = g_vh; Cl = g_vl; N = KVH; bn = (bx - 20) * 128; }
    gemm_core(g_xh, g_xl, Bh, Bl, bias, Ch, Cl, nullptr, bm, bn, N, HID);
}

__global__ __launch_bounds__(256) void o_gemm(float* __restrict__ out)
{
    gemm_core(g_oh, g_ol, g_woh, g_wol, nullptr, nullptr, nullptr, out,
              blockIdx.y * 128, blockIdx.x * 128, HID, HID);
}

// ---------------------------------------------------------------------------
// RoPE in-place on split planes (position_ids are int32)
// ---------------------------------------------------------------------------
__global__ void rope_sp(bf16* __restrict__ hi, bf16* __restrict__ lo,
                        const int* __restrict__ pos_ids,
                        int nheads, int stride, int total)
{
    int idx = blockIdx.x * blockDim.x + threadIdx.x;
    if (idx >= total) return;
    int i = idx & 63;
    int h = (idx >> 6) % nheads;
    int s = idx / (64 * nheads);

    float pos = (float)pos_ids[s];
    float inv = expf(-(float)(2 * i) * (1.0f / 128.0f) * 9.210340371976184f);
    float ang = pos * inv;
    float c, sn;
    sincosf(ang, &sn, &c);

    size_t base = (size_t)s * stride + h * HD;
    float x0 = __bfloat162float(hi[base + i])      + __bfloat162float(lo[base + i]);
    float x1 = __bfloat162float(hi[base + i + 64]) + __bfloat162float(lo[base + i + 64]);
    float y0 = x0 * c - x1 * sn;
    float y1 = x1 * c + x0 * sn;
    bf16 h0 = __float2bfloat16(y0);
    bf16 h1 = __float2bfloat16(y1);
    hi[base + i]      = h0;
    lo[base + i]      = __float2bfloat16(y0 - __bfloat162float(h0));
    hi[base + i + 64] = h1;
    lo[base + i + 64] = __float2bfloat16(y1 - __bfloat162float(h1));
}

// ---------------------------------------------------------------------------
// Flash attention, warp-mma bf16 3-term, KV double-buffered. Causal, GQA 4:1.
// Block: 128 q-rows x one head, 256 threads (8 warps x 16 rows), KV tile 64.
// ---------------------------------------------------------------------------
#define FLQ 136
#define KVSET (4 * 64 * FLQ)                          // elems per KV buffer
#define FSMEM ((2 * 128 * FLQ + 2 * KVSET) * 2)       // 208896 bytes

__device__ __forceinline__ void flash_kv_load(
    bf16* kvbase, int kvh, int j0, int tid)
{
#pragma unroll
    for (int j = 0; j < 16; j++) {
        const int plane = j >> 2;
        const int tt = tid * 4 + (j & 3);             // 0..1023
        const int r = tt >> 4, c16 = tt & 15;
        const bf16* src;
        if (plane == 0)      src = g_kh;
        else if (plane == 1) src = g_kl;
        else if (plane == 2) src = g_vh;
        else                 src = g_vl;
        src += (size_t)(j0 + r) * KVH + kvh * HD + c16 * 8;
        uint32_t dst = smem_u32(kvbase + plane * 64 * FLQ + r * FLQ + c16 * 8);
        CP_ASYNC16(dst, src);
    }
}

__global__ __launch_bounds__(256) void flash_sp()
{
    extern __shared__ bf16 sm[];
    bf16* Qh = sm;
    bf16* Ql = Qh + 128 * FLQ;
    bf16* KV = Ql + 128 * FLQ;    // 2 buffers x 4 planes x 64*FLQ

    const int h   = blockIdx.y;
    const int qt  = blockIdx.x;
    const int q0  = qt * 128;
    const int kvh = h >> 2;
    const int tid = threadIdx.x, warp = tid >> 5, lane = tid & 31;
    const int g   = lane >> 2, t2 = (lane & 3) * 2;

    // Q tile via cp.async (2 planes, 128x128)
#pragma unroll
    for (int j = 0; j < 16; j++) {
        const int plane = j >> 3;
        const int t = tid * 8 + (j & 7);
        const int r = t >> 4, c16 = t & 15;
        const bf16* src = (plane ? g_ql : g_qh) + (size_t)(q0 + r) * HID + h * HD + c16 * 8;
        uint32_t dst = smem_u32((plane ? Ql : Qh) + r * FLQ + c16 * 8);
        CP_ASYNC16(dst, src);
    }
    CP_COMMIT;

    float m0 = -1e30f, m1 = -1e30f, l0 = 0.f, l1 = 0.f;
    float oacc[16][4];
#pragma unroll
    for (int nf = 0; nf < 16; nf++)
#pragma unroll
        for (int q = 0; q < 4; q++) oacc[nf][q] = 0.f;

    const float scale = 0.08838834764831845f;
    const int mrow = warp * 16;
    const int r0 = q0 + mrow + g, r1 = r0 + 8;
    const int wmax = q0 + mrow + 15;
    const int arow = (lane & 7) + ((lane & 8) ? 8 : 0);
    const int brow = lane & 7;
    const int vrow = lane & 15;

    const int ntiles = 2 * qt + 2;

    // preload tile 0 into buffer 0
    flash_kv_load(KV, kvh, 0, tid);
    CP_COMMIT;

    for (int t = 0; t < ntiles; t++) {
        const int j0 = t * 64;
        __syncthreads();   // all warps done computing tile t-1 (protects buf (t+1)&1)
        if (t + 1 < ntiles) {
            flash_kv_load(KV + ((t + 1) & 1) * KVSET, kvh, (t + 1) * 64, tid);
            CP_COMMIT;
            CP_WAIT(1);
        } else {
            CP_WAIT(0);
        }
        __syncthreads();   // tile t data visible to all threads
        if (j0 > wmax) continue;

        bf16* Kh = KV + (t & 1) * KVSET;
        bf16* Kl = Kh + 64 * FLQ;
        bf16* Vh = Kl + 64 * FLQ;
        bf16* Vl = Vh + 64 * FLQ;

        // ---- S = Q K^T ----
        float s[8][4];
#pragma unroll
        for (int nf = 0; nf < 8; nf++)
#pragma unroll
            for (int q = 0; q < 4; q++) s[nf][q] = 0.f;

#pragma unroll
        for (int kt = 0; kt < 128; kt += 16) {
            const int acol = kt + ((lane & 16) ? 8 : 0);
            uint32_t qh[4], ql[4];
            LDSM_X4(qh[0], qh[1], qh[2], qh[3], smem_u32(&Qh[(mrow + arow) * FLQ + acol]));
            LDSM_X4(ql[0], ql[1], ql[2], ql[3], smem_u32(&Ql[(mrow + arow) * FLQ + acol]));
            const int bcol = kt + ((lane & 8) ? 8 : 0);
            // process nf in pairs; term-major within pair (2 indep chains)
#pragma unroll
            for (int np = 0; np < 4; np++) {
                const int nA = 2 * np, nB = 2 * np + 1;
                uint32_t bhA0, bhA1, blA0, blA1, bhB0, bhB1, blB0, blB1;
                LDSM_X2(bhA0, bhA1, smem_u32(&Kh[(nA * 8 + brow) * FLQ + bcol]));
                LDSM_X2(blA0, blA1, smem_u32(&Kl[(nA * 8 + brow) * FLQ + bcol]));
                LDSM_X2(bhB0, bhB1, smem_u32(&Kh[(nB * 8 + brow) * FLQ + bcol]));
                LDSM_X2(blB0, blB1, smem_u32(&Kl[(nB * 8 + brow) * FLQ + bcol]));
                MMA_BF16(s[nA], qh[0], qh[1], qh[2], qh[3], bhA0, bhA1);
                MMA_BF16(s[nB], qh[0], qh[1], qh[2], qh[3], bhB0, bhB1);
                MMA_BF16(s[nA], qh[0], qh[1], qh[2], qh[3], blA0, blA1);
                MMA_BF16(s[nB], qh[0], qh[1], qh[2], qh[3], blB0, blB1);
                MMA_BF16(s[nA], ql[0], ql[1], ql[2], ql[3], bhA0, bhA1);
                MMA_BF16(s[nB], ql[0], ql[1], ql[2], ql[3], bhB0, bhB1);
            }
        }

#pragma unroll
        for (int nf = 0; nf < 8; nf++)
#pragma unroll
            for (int q = 0; q < 4; q++) s[nf][q] *= scale;

        if (j0 + 63 > r0) {
#pragma unroll
            for (int nf = 0; nf < 8; nf++) {
                const int c0 = j0 + nf * 8 + t2;
                if (c0     > r0) s[nf][0] = -1e30f;
                if (c0 + 1 > r0) s[nf][1] = -1e30f;
                if (c0     > r1) s[nf][2] = -1e30f;
                if (c0 + 1 > r1) s[nf][3] = -1e30f;
            }
        }

        // ---- online softmax ----
        float mx0 = -1e30f, mx1 = -1e30f;
#pragma unroll
        for (int nf = 0; nf < 8; nf++) {
            mx0 = fmaxf(mx0, fmaxf(s[nf][0], s[nf][1]));
            mx1 = fmaxf(mx1, fmaxf(s[nf][2], s[nf][3]));
        }
        mx0 = fmaxf(mx0, __shfl_xor_sync(0xffffffffu, mx0, 1));
        mx0 = fmaxf(mx0, __shfl_xor_sync(0xffffffffu, mx0, 2));
        mx1 = fmaxf(mx1, __shfl_xor_sync(0xffffffffu, mx1, 1));
        mx1 = fmaxf(mx1, __shfl_xor_sync(0xffffffffu, mx1, 2));
        const float mn0 = fmaxf(m0, mx0), mn1 = fmaxf(m1, mx1);
        const float a0 = __expf(m0 - mn0), a1 = __expf(m1 - mn1);
        float sum0 = 0.f, sum1 = 0.f;
#pragma unroll
        for (int nf = 0; nf < 8; nf++) {
            s[nf][0] = __expf(s[nf][0] - mn0);
            s[nf][1] = __expf(s[nf][1] - mn0);
            s[nf][2] = __expf(s[nf][2] - mn1);
            s[nf][3] = __expf(s[nf][3] - mn1);
            sum0 += s[nf][0] + s[nf][1];
            sum1 += s[nf][2] + s[nf][3];
        }
        sum0 += __shfl_xor_sync(0xffffffffu, sum0, 1);
        sum0 += __shfl_xor_sync(0xffffffffu, sum0, 2);
        sum1 += __shfl_xor_sync(0xffffffffu, sum1, 1);
        sum1 += __shfl_xor_sync(0xffffffffu, sum1, 2);
        l0 = l0 * a0 + sum0;  l1 = l1 * a1 + sum1;
        m0 = mn0;             m1 = mn1;
#pragma unroll
        for (int nf = 0; nf < 16; nf++) {
            oacc[nf][0] *= a0; oacc[nf][1] *= a0;
            oacc[nf][2] *= a1; oacc[nf][3] *= a1;
        }

        // ---- pack P fragments ----
        uint32_t pah[4][4], pal[4][4];
#pragma unroll
        for (int j = 0; j < 4; j++) {
            pah[j][0] = pack2_hi(s[2*j][0],   s[2*j][1]);
            pah[j][1] = pack2_hi(s[2*j][2],   s[2*j][3]);
            pah[j][2] = pack2_hi(s[2*j+1][0], s[2*j+1][1]);
            pah[j][3] = pack2_hi(s[2*j+1][2], s[2*j+1][3]);
            pal[j][0] = pack2_lo(s[2*j][0],   s[2*j][1]);
            pal[j][1] = pack2_lo(s[2*j][2],   s[2*j][3]);
            pal[j][2] = pack2_lo(s[2*j+1][0], s[2*j+1][1]);
            pal[j][3] = pack2_lo(s[2*j+1][2], s[2*j+1][3]);
        }

        // ---- O += P @ V (pairwise term-interleaved) ----
#pragma unroll
        for (int j = 0; j < 4; j++) {
#pragma unroll
            for (int np = 0; np < 8; np++) {
                const int nA = 2 * np, nB = 2 * np + 1;
                uint32_t bhA0, bhA1, blA0, blA1, bhB0, bhB1, blB0, blB1;
                LDSM_X2T(bhA0, bhA1, smem_u32(&Vh[(16 * j + vrow) * FLQ + nA * 8]));
                LDSM_X2T(blA0, blA1, smem_u32(&Vl[(16 * j + vrow) * FLQ + nA * 8]));
                LDSM_X2T(bhB0, bhB1, smem_u32(&Vh[(16 * j + vrow) * FLQ + nB * 8]));
                LDSM_X2T(blB0, blB1, smem_u32(&Vl[(16 * j + vrow) * FLQ + nB * 8]));
                MMA_BF16(oacc[nA], pah[j][0], pah[j][1], pah[j][2], pah[j][3], bhA0, bhA1);
                MMA_BF16(oacc[nB], pah[j][0], pah[j][1], pah[j][2], pah[j][3], bhB0, bhB1);
                MMA_BF16(oacc[nA], pah[j][0], pah[j][1], pah[j][2], pah[j][3], blA0, blA1);
                MMA_BF16(oacc[nB], pah[j][0], pah[j][1], pah[j][2], pah[j][3], blB0, blB1);
                MMA_BF16(oacc[nA], pal[j][0], pal[j][1], pal[j][2], pal[j][3], bhA0, bhA1);
                MMA_BF16(oacc[nB], pal[j][0], pal[j][1], pal[j][2], pal[j][3], bhB0, bhB1);
            }
        }
    }

    // ---- normalize + store split planes ----
    const float inv0 = 1.f / l0, inv1 = 1.f / l1;
#pragma unroll
    for (int nf = 0; nf < 16; nf++) {
        const int col = h * HD + nf * 8 + t2;
        float v0 = oacc[nf][0] * inv0, v1 = oacc[nf][1] * inv0;
        float v2 = oacc[nf][2] * inv1, v3 = oacc[nf][3] * inv1;
        *(uint32_t*)&g_oh[(size_t)r0 * HID + col] = pack2_hi(v0, v1);
        *(uint32_t*)&g_ol[(size_t)r0 * HID + col] = pack2_lo(v0, v1);
        *(uint32_t*)&g_oh[(size_t)r1 * HID + col] = pack2_hi(v2, v3);
        *(uint32_t*)&g_ol[(size_t)r1 * HID + col] = pack2_lo(v2, v3);
    }
}

// ---------------------------------------------------------------------------

extern "C" void kernel_launch(void* const* d_in, const int* in_sizes, int n_in,
                              void* d_out, int out_size)
{
    const float* x   = (const float*)d_in[0];
    /* d_in[1] attention_mask: exact causal triu(-inf), applied analytically */
    const int*   pos = (const int*)d_in[2];
    const float* wq  = (const float*)d_in[3];
    const float* bq  = (const float*)d_in[4];
    const float* wk  = (const float*)d_in[5];
    const float* bk  = (const float*)d_in[6];
    const float* wv  = (const float*)d_in[7];
    const float* bv  = (const float*)d_in[8];
    const float* wo  = (const float*)d_in[9];
    float*       out = (float*)d_out;

    bf16 *xh, *xl, *wqh, *wql, *wkh, *wkl, *wvh, *wvl, *woh, *wol;
    bf16 *qh, *ql, *kh, *kl;
    cudaGetSymbolAddress((void**)&xh,  g_xh);  cudaGetSymbolAddress((void**)&xl,  g_xl);
    cudaGetSymbolAddress((void**)&wqh, g_wqh); cudaGetSymbolAddress((void**)&wql, g_wql);
    cudaGetSymbolAddress((void**)&wkh, g_wkh); cudaGetSymbolAddress((void**)&wkl, g_wkl);
    cudaGetSymbolAddress((void**)&wvh, g_wvh); cudaGetSymbolAddress((void**)&wvl, g_wvl);
    cudaGetSymbolAddress((void**)&woh, g_woh); cudaGetSymbolAddress((void**)&wol, g_wol);
    cudaGetSymbolAddress((void**)&qh,  g_qh);  cudaGetSymbolAddress((void**)&ql,  g_ql);
    cudaGetSymbolAddress((void**)&kh,  g_kh);  cudaGetSymbolAddress((void**)&kl,  g_kl);

    cudaFuncSetAttribute(qkv_gemm, cudaFuncAttributeMaxDynamicSharedMemorySize, GSMEM);
    cudaFuncSetAttribute(o_gemm,   cudaFuncAttributeMaxDynamicSharedMemorySize, GSMEM);
    cudaFuncSetAttribute(flash_sp, cudaFuncAttributeMaxDynamicSharedMemorySize, FSMEM);

    // one-shot splits (memory bound)
    split_f32<<<(S_LEN * HID / 4 + 255) / 256, 256>>>(x,  xh,  xl,  S_LEN * HID / 4);
    split_f32<<<(HID * HID / 4 + 255) / 256, 256>>>(wq, wqh, wql, HID * HID / 4);
    split_f32<<<(KVH * HID / 4 + 255) / 256, 256>>>(wk, wkh, wkl, KVH * HID / 4);
    split_f32<<<(KVH * HID / 4 + 255) / 256, 256>>>(wv, wvh, wvl, KVH * HID / 4);
    split_f32<<<(HID * HID / 4 + 255) / 256, 256>>>(wo, woh, wol, HID * HID / 4);

    // fused QKV projection
    qkv_gemm<<<dim3(24, 16), 256, GSMEM>>>(bq, bk, bv);

    // RoPE on split planes
    {
        int totq = S_LEN * NH * 64;
        rope_sp<<<(totq + 255) / 256, 256>>>(qh, ql, pos, NH, HID, totq);
        int totk = S_LEN * NKV * 64;
        rope_sp<<<(totk + 255) / 256, 256>>>(kh, kl, pos, NKV, KVH, totk);
    }

    // flash attention (KV double-buffered)
    flash_sp<<<dim3(S_LEN / 128, NH), 256, FSMEM>>>();

    // output projection -> fp32
    o_gemm<<<dim3(HID / 128, S_LEN / 128), 256, GSMEM>>>(out);
}

// round 11
// speedup vs baseline: 2.9787x; 1.0593x over previous
#include <cuda_runtime.h>
#include <cuda_bf16.h>
#include <math.h>
#include <stdint.h>

#define S_LEN 2048
#define HID   2048
#define NH    16
#define NKV   4
#define HD    128
#define KVH   512

typedef __nv_bfloat16 bf16;

// ------------------- split-plane scratch (bf16 hi/lo) -------------------
__device__ bf16 g_xh[S_LEN * HID], g_xl[S_LEN * HID];
__device__ bf16 g_wqh[HID * HID],  g_wql[HID * HID];
__device__ bf16 g_wkh[KVH * HID],  g_wkl[KVH * HID];
__device__ bf16 g_wvh[KVH * HID],  g_wvl[KVH * HID];
__device__ bf16 g_woh[HID * HID],  g_wol[HID * HID];
__device__ bf16 g_qh[S_LEN * HID], g_ql[S_LEN * HID];
__device__ bf16 g_kh[S_LEN * KVH], g_kl[S_LEN * KVH];
__device__ bf16 g_vh[S_LEN * KVH], g_vl[S_LEN * KVH];
__device__ bf16 g_oh[S_LEN * HID], g_ol[S_LEN * HID];

// split-K fp32 partials (2 halves each)
__device__ float g_pq[2 * S_LEN * HID];
__device__ float g_pk[2 * S_LEN * KVH];
__device__ float g_pv[2 * S_LEN * KVH];

__device__ __forceinline__ uint32_t smem_u32(const void* p) {
    return (uint32_t)__cvta_generic_to_shared(p);
}

#define MMA_BF16(c, a0, a1, a2, a3, b0, b1)                                 \
    asm("mma.sync.aligned.m16n8k16.row.col.f32.bf16.bf16.f32 "              \
        "{%0,%1,%2,%3},{%4,%5,%6,%7},{%8,%9},{%0,%1,%2,%3};"                \
        : "+f"(c[0]), "+f"(c[1]), "+f"(c[2]), "+f"(c[3])                    \
        : "r"(a0), "r"(a1), "r"(a2), "r"(a3), "r"(b0), "r"(b1))

#define LDSM_X4(r0, r1, r2, r3, addr)                                       \
    asm("ldmatrix.sync.aligned.m8n8.x4.shared.b16 {%0,%1,%2,%3},[%4];"      \
        : "=r"(r0), "=r"(r1), "=r"(r2), "=r"(r3) : "r"(addr))

#define LDSM_X2(r0, r1, addr)                                               \
    asm("ldmatrix.sync.aligned.m8n8.x2.shared.b16 {%0,%1},[%2];"            \
        : "=r"(r0), "=r"(r1) : "r"(addr))

#define LDSM_X2T(r0, r1, addr)                                              \
    asm("ldmatrix.sync.aligned.m8n8.x2.trans.shared.b16 {%0,%1},[%2];"      \
        : "=r"(r0), "=r"(r1) : "r"(addr))

#define CP_ASYNC16(dst, src)                                                \
    asm volatile("cp.async.cg.shared.global [%0],[%1],16;"                  \
                 :: "r"(dst), "l"(src))
#define CP_COMMIT  asm volatile("cp.async.commit_group;" ::: "memory")
#define CP_WAIT(n) asm volatile("cp.async.wait_group %0;" :: "n"(n) : "memory")

__device__ __forceinline__ uint32_t pack2_hi(float x, float y) {
    __nv_bfloat162 t;
    t.x = __float2bfloat16(x); t.y = __float2bfloat16(y);
    return *(uint32_t*)&t;
}
__device__ __forceinline__ uint32_t pack2_lo(float x, float y) {
    __nv_bfloat162 t;
    t.x = __float2bfloat16(x - __bfloat162float(__float2bfloat16(x)));
    t.y = __float2bfloat16(y - __bfloat162float(__float2bfloat16(y)));
    return *(uint32_t*)&t;
}

// ---------------------------------------------------------------------------
// f32 -> (hi, lo) bf16 plane split (one-shot, memory bound)
// ---------------------------------------------------------------------------
__global__ void split_f32(const float* __restrict__ in,
                          bf16* __restrict__ hi, bf16* __restrict__ lo, int n4)
{
    int i = blockIdx.x * blockDim.x + threadIdx.x;
    if (i >= n4) return;
    float4 v = ((const float4*)in)[i];
    ((uint32_t*)hi)[i * 2]     = pack2_hi(v.x, v.y);
    ((uint32_t*)hi)[i * 2 + 1] = pack2_hi(v.z, v.w);
    ((uint32_t*)lo)[i * 2]     = pack2_lo(v.x, v.y);
    ((uint32_t*)lo)[i * 2 + 1] = pack2_lo(v.z, v.w);
}

// ---------------------------------------------------------------------------
// split-K combine: out = split(p0 + p1 + bias)
// ---------------------------------------------------------------------------
__global__ void combine_sp(const float* __restrict__ p0,
                           const float* __restrict__ p1,
                           const float* __restrict__ bias,
                           bf16* __restrict__ hi, bf16* __restrict__ lo,
                           int N, int n4)
{
    int i = blockIdx.x * blockDim.x + threadIdx.x;
    if (i >= n4) return;
    float4 a = ((const float4*)p0)[i];
    float4 b = ((const float4*)p1)[i];
    const int col = (i * 4) & (N - 1);   // N is a power of two here
    float v0 = a.x + b.x, v1 = a.y + b.y, v2 = a.z + b.z, v3 = a.w + b.w;
    if (bias) {
        v0 += bias[col]; v1 += bias[col + 1]; v2 += bias[col + 2]; v3 += bias[col + 3];
    }
    ((uint32_t*)hi)[i * 2]     = pack2_hi(v0, v1);
    ((uint32_t*)hi)[i * 2 + 1] = pack2_hi(v2, v3);
    ((uint32_t*)lo)[i * 2]     = pack2_lo(v0, v1);
    ((uint32_t*)lo)[i * 2 + 1] = pack2_lo(v2, v3);
}

// ---------------------------------------------------------------------------
// GEMM core: C[M,N] = A @ B^T over K range [kstart, kstart+klen). bf16 planes
// in, 3-term MMA, term-major. 128x128 tile, BK=32, double-buffered cp.async.
// ---------------------------------------------------------------------------
#define PLANE_B 10240          // 128 rows * 40 elems * 2B
#define BUF_B   40960          // 4 planes
#define GSMEM   81920          // 2 buffers

__device__ __forceinline__ void gemm_prefetch(
    uint32_t s_base, int buf,
    const bf16* __restrict__ Ahg, const bf16* __restrict__ Alg,
    const bf16* __restrict__ Bhg, const bf16* __restrict__ Blg,
    int bm, int bn, int K, int k0, int tid)
{
#pragma unroll
    for (int j = 0; j < 8; j++) {
        const int plane = j >> 1;
        const int t = tid * 2 + (j & 1);     // 0..511
        const int r = t >> 2, c8 = t & 3;
        const bf16* src = (plane == 0) ? Ahg : (plane == 1) ? Alg
                        : (plane == 2) ? Bhg : Blg;
        const int rowbase = (plane < 2) ? bm : bn;
        uint32_t dst = s_base + (uint32_t)buf * BUF_B + (uint32_t)plane * PLANE_B
                     + (uint32_t)(r * 40 + c8 * 8) * 2;
        CP_ASYNC16(dst, src + (size_t)(rowbase + r) * K + k0 + c8 * 8);
    }
}

__device__ __forceinline__ void gemm_core(
    const bf16* __restrict__ Ahg, const bf16* __restrict__ Alg,
    const bf16* __restrict__ Bhg, const bf16* __restrict__ Blg,
    const float* __restrict__ bias,
    bf16* __restrict__ Ch, bf16* __restrict__ Cl, float* __restrict__ Cf,
    int bm, int bn, int N, int K, int kstart, int klen)
{
    extern __shared__ bf16 smbuf[];
    const uint32_t s_base = smem_u32(smbuf);
    const int tid  = threadIdx.x, warp = tid >> 5, lane = tid & 31;
    const int wm   = (warp & 1) * 64, wn = (warp >> 1) * 32;
    const int g    = lane >> 2, t2 = (lane & 3) * 2;
    const int arow = (lane & 7) + ((lane & 8) ? 8 : 0);
    const int brow = lane & 7;

    float acc[4][4][4];
#pragma unroll
    for (int mi = 0; mi < 4; mi++)
#pragma unroll
        for (int ni = 0; ni < 4; ni++)
#pragma unroll
            for (int q = 0; q < 4; q++) acc[mi][ni][q] = 0.f;

    const int nchunk = klen >> 5;
    gemm_prefetch(s_base, 0, Ahg, Alg, Bhg, Blg, bm, bn, K, kstart, tid);
    CP_COMMIT;

    for (int c = 0; c < nchunk; c++) {
        if (c + 1 < nchunk) {
            gemm_prefetch(s_base, (c + 1) & 1, Ahg, Alg, Bhg, Blg,
                          bm, bn, K, kstart + ((c + 1) << 5), tid);
            CP_COMMIT;
            CP_WAIT(1);
        } else {
            CP_WAIT(0);
        }
        __syncthreads();

        const uint32_t bufb = s_base + (uint32_t)(c & 1) * BUF_B;
        const uint32_t aAh = bufb, aAl = bufb + PLANE_B;
        const uint32_t aBh = bufb + 2 * PLANE_B, aBl = bufb + 3 * PLANE_B;

#pragma unroll
        for (int kt = 0; kt < 32; kt += 16) {
            const int acol = kt + ((lane & 16) ? 8 : 0);
            uint32_t ah[4][4], al[4][4];
#pragma unroll
            for (int mi = 0; mi < 4; mi++) {
                const uint32_t off = (uint32_t)((wm + mi * 16 + arow) * 40 + acol) * 2;
                LDSM_X4(ah[mi][0], ah[mi][1], ah[mi][2], ah[mi][3], aAh + off);
                LDSM_X4(al[mi][0], al[mi][1], al[mi][2], al[mi][3], aAl + off);
            }
            const int bcol = kt + ((lane & 8) ? 8 : 0);
#pragma unroll
            for (int ni = 0; ni < 4; ni++) {
                const uint32_t boff = (uint32_t)((wn + ni * 8 + brow) * 40 + bcol) * 2;
                uint32_t bh0, bh1, bl0, bl1;
                LDSM_X2(bh0, bh1, aBh + boff);
                LDSM_X2(bl0, bl1, aBl + boff);
#pragma unroll
                for (int mi = 0; mi < 4; mi++)
                    MMA_BF16(acc[mi][ni], ah[mi][0], ah[mi][1], ah[mi][2], ah[mi][3], bh0, bh1);
#pragma unroll
                for (int mi = 0; mi < 4; mi++)
                    MMA_BF16(acc[mi][ni], ah[mi][0], ah[mi][1], ah[mi][2], ah[mi][3], bl0, bl1);
#pragma unroll
                for (int mi = 0; mi < 4; mi++)
                    MMA_BF16(acc[mi][ni], al[mi][0], al[mi][1], al[mi][2], al[mi][3], bh0, bh1);
            }
        }
        __syncthreads();
    }

#pragma unroll
    for (int mi = 0; mi < 4; mi++) {
#pragma unroll
        for (int ni = 0; ni < 4; ni++) {
            const int row = bm + wm + mi * 16 + g;
            const int col = bn + wn + ni * 8 + t2;
            float b0 = bias ? bias[col] : 0.f;
            float b1 = bias ? bias[col + 1] : 0.f;
            float v0 = acc[mi][ni][0] + b0, v1 = acc[mi][ni][1] + b1;
            float v2 = acc[mi][ni][2] + b0, v3 = acc[mi][ni][3] + b1;
            if (Cf) {
                float2 w0; w0.x = v0; w0.y = v1;
                float2 w1; w1.x = v2; w1.y = v3;
                *(float2*)&Cf[(size_t)row * N + col]       = w0;
                *(float2*)&Cf[(size_t)(row + 8) * N + col] = w1;
            } else {
                *(uint32_t*)&Ch[(size_t)row * N + col]       = pack2_hi(v0, v1);
                *(uint32_t*)&Cl[(size_t)row * N + col]       = pack2_lo(v0, v1);
                *(uint32_t*)&Ch[(size_t)(row + 8) * N + col] = pack2_hi(v2, v3);
                *(uint32_t*)&Cl[(size_t)(row + 8) * N + col] = pack2_lo(v2, v3);
            }
        }
    }
}

// QKV split-K: bx = tilecol*2 + ks. tilecol 0..15 -> Q, 16..19 -> K, 20..23 -> V
__global__ __launch_bounds__(256) void qkv_gemm_sk()
{
    const int bx = blockIdx.x;            // 0..47
    const int tc = bx >> 1, ks = bx & 1;
    const int bm = blockIdx.y * 128;
    const int kstart = ks * (HID / 2);
    if (tc < 16)
        gemm_core(g_xh, g_xl, g_wqh, g_wql, nullptr, nullptr, nullptr,
                  g_pq + (size_t)ks * S_LEN * HID,
                  bm, tc * 128, HID, HID, kstart, HID / 2);
    else if (tc < 20)
        gemm_core(g_xh, g_xl, g_wkh, g_wkl, nullptr, nullptr, nullptr,
                  g_pk + (size_t)ks * S_LEN * KVH,
                  bm, (tc - 16) * 128, KVH, HID, kstart, HID / 2);
    else
        gemm_core(g_xh, g_xl, g_wvh, g_wvl, nullptr, nullptr, nullptr,
                  g_pv + (size_t)ks * S_LEN * KVH,
                  bm, (tc - 20) * 128, KVH, HID, kstart, HID / 2);
}

__global__ __launch_bounds__(256) void o_gemm(float* __restrict__ out)
{
    gemm_core(g_oh, g_ol, g_woh, g_wol, nullptr, nullptr, nullptr, out,
              blockIdx.y * 128, blockIdx.x * 128, HID, HID, 0, HID);
}

// ---------------------------------------------------------------------------
// RoPE in-place on split planes (position_ids are int32)
// ---------------------------------------------------------------------------
__global__ void rope_sp(bf16* __restrict__ hi, bf16* __restrict__ lo,
                        const int* __restrict__ pos_ids,
                        int nheads, int stride, int total)
{
    int idx = blockIdx.x * blockDim.x + threadIdx.x;
    if (idx >= total) return;
    int i = idx & 63;
    int h = (idx >> 6) % nheads;
    int s = idx / (64 * nheads);

    float pos = (float)pos_ids[s];
    float inv = expf(-(float)(2 * i) * (1.0f / 128.0f) * 9.210340371976184f);
    float ang = pos * inv;
    float c, sn;
    sincosf(ang, &sn, &c);

    size_t base = (size_t)s * stride + h * HD;
    float x0 = __bfloat162float(hi[base + i])      + __bfloat162float(lo[base + i]);
    float x1 = __bfloat162float(hi[base + i + 64]) + __bfloat162float(lo[base + i + 64]);
    float y0 = x0 * c - x1 * sn;
    float y1 = x1 * c + x0 * sn;
    bf16 h0 = __float2bfloat16(y0);
    bf16 h1 = __float2bfloat16(y1);
    hi[base + i]      = h0;
    lo[base + i]      = __float2bfloat16(y0 - __bfloat162float(h0));
    hi[base + i + 64] = h1;
    lo[base + i + 64] = __float2bfloat16(y1 - __bfloat162float(h1));
}

// ---------------------------------------------------------------------------
// Flash attention, warp-mma bf16 3-term, KV double-buffered, qt-PAIRED:
// block bx handles q-tiles (15-bx) then (bx) -> uniform 36 KV-tiles/block,
// 128 blocks = single balanced wave. Causal, GQA 4:1.
// ---------------------------------------------------------------------------
#define FLQ 136
#define KVSET (4 * 64 * FLQ)
#define FSMEM ((2 * 128 * FLQ + 2 * KVSET) * 2)       // 208896 bytes

__device__ __forceinline__ void flash_kv_load(
    bf16* kvbase, int kvh, int j0, int tid)
{
#pragma unroll
    for (int j = 0; j < 16; j++) {
        const int plane = j >> 2;
        const int tt = tid * 4 + (j & 3);
        const int r = tt >> 4, c16 = tt & 15;
        const bf16* src;
        if (plane == 0)      src = g_kh;
        else if (plane == 1) src = g_kl;
        else if (plane == 2) src = g_vh;
        else                 src = g_vl;
        src += (size_t)(j0 + r) * KVH + kvh * HD + c16 * 8;
        uint32_t dst = smem_u32(kvbase + plane * 64 * FLQ + r * FLQ + c16 * 8);
        CP_ASYNC16(dst, src);
    }
}

__global__ __launch_bounds__(256) void flash_sp()
{
    extern __shared__ bf16 sm[];
    bf16* Qh = sm;
    bf16* Ql = Qh + 128 * FLQ;
    bf16* KV = Ql + 128 * FLQ;

    const int h   = blockIdx.y;
    const int kvh = h >> 2;
    const int tid = threadIdx.x, warp = tid >> 5, lane = tid & 31;
    const int g   = lane >> 2, t2 = (lane & 3) * 2;
    const float scale = 0.08838834764831845f;
    const int mrow = warp * 16;
    const int arow = (lane & 7) + ((lane & 8) ? 8 : 0);
    const int brow = lane & 7;
    const int vrow = lane & 15;

    for (int pass = 0; pass < 2; pass++) {
        const int qt = pass == 0 ? (15 - (int)blockIdx.x) : (int)blockIdx.x;
        const int q0 = qt * 128;

        __syncthreads();   // prior pass fully done with Qh/Ql/KV

        // Q tile via cp.async (2 planes, 128x128)
#pragma unroll
        for (int j = 0; j < 16; j++) {
            const int plane = j >> 3;
            const int t = tid * 8 + (j & 7);
            const int r = t >> 4, c16 = t & 15;
            const bf16* src = (plane ? g_ql : g_qh) + (size_t)(q0 + r) * HID + h * HD + c16 * 8;
            uint32_t dst = smem_u32((plane ? Ql : Qh) + r * FLQ + c16 * 8);
            CP_ASYNC16(dst, src);
        }
        CP_COMMIT;

        float m0 = -1e30f, m1 = -1e30f, l0 = 0.f, l1 = 0.f;
        float oacc[16][4];
#pragma unroll
        for (int nf = 0; nf < 16; nf++)
#pragma unroll
            for (int q = 0; q < 4; q++) oacc[nf][q] = 0.f;

        const int r0 = q0 + mrow + g, r1 = r0 + 8;
        const int wmax = q0 + mrow + 15;
        const int ntiles = 2 * qt + 2;

        flash_kv_load(KV, kvh, 0, tid);
        CP_COMMIT;

        for (int t = 0; t < ntiles; t++) {
            const int j0 = t * 64;
            __syncthreads();
            if (t + 1 < ntiles) {
                flash_kv_load(KV + ((t + 1) & 1) * KVSET, kvh, (t + 1) * 64, tid);
                CP_COMMIT;
                CP_WAIT(1);
            } else {
                CP_WAIT(0);
            }
            __syncthreads();
            if (j0 > wmax) continue;

            bf16* Kh = KV + (t & 1) * KVSET;
            bf16* Kl = Kh + 64 * FLQ;
            bf16* Vh = Kl + 64 * FLQ;
            bf16* Vl = Vh + 64 * FLQ;

            // ---- S = Q K^T ----
            float s[8][4];
#pragma unroll
            for (int nf = 0; nf < 8; nf++)
#pragma unroll
                for (int q = 0; q < 4; q++) s[nf][q] = 0.f;

#pragma unroll
            for (int kt = 0; kt < 128; kt += 16) {
                const int acol = kt + ((lane & 16) ? 8 : 0);
                uint32_t qh[4], ql[4];
                LDSM_X4(qh[0], qh[1], qh[2], qh[3], smem_u32(&Qh[(mrow + arow) * FLQ + acol]));
                LDSM_X4(ql[0], ql[1], ql[2], ql[3], smem_u32(&Ql[(mrow + arow) * FLQ + acol]));
                const int bcol = kt + ((lane & 8) ? 8 : 0);
#pragma unroll
                for (int np = 0; np < 4; np++) {
                    const int nA = 2 * np, nB = 2 * np + 1;
                    uint32_t bhA0, bhA1, blA0, blA1, bhB0, bhB1, blB0, blB1;
                    LDSM_X2(bhA0, bhA1, smem_u32(&Kh[(nA * 8 + brow) * FLQ + bcol]));
                    LDSM_X2(blA0, blA1, smem_u32(&Kl[(nA * 8 + brow) * FLQ + bcol]));
                    LDSM_X2(bhB0, bhB1, smem_u32(&Kh[(nB * 8 + brow) * FLQ + bcol]));
                    LDSM_X2(blB0, blB1, smem_u32(&Kl[(nB * 8 + brow) * FLQ + bcol]));
                    MMA_BF16(s[nA], qh[0], qh[1], qh[2], qh[3], bhA0, bhA1);
                    MMA_BF16(s[nB], qh[0], qh[1], qh[2], qh[3], bhB0, bhB1);
                    MMA_BF16(s[nA], qh[0], qh[1], qh[2], qh[3], blA0, blA1);
                    MMA_BF16(s[nB], qh[0], qh[1], qh[2], qh[3], blB0, blB1);
                    MMA_BF16(s[nA], ql[0], ql[1], ql[2], ql[3], bhA0, bhA1);
                    MMA_BF16(s[nB], ql[0], ql[1], ql[2], ql[3], bhB0, bhB1);
                }
            }

#pragma unroll
            for (int nf = 0; nf < 8; nf++)
#pragma unroll
                for (int q = 0; q < 4; q++) s[nf][q] *= scale;

            if (j0 + 63 > r0) {
#pragma unroll
                for (int nf = 0; nf < 8; nf++) {
                    const int c0 = j0 + nf * 8 + t2;
                    if (c0     > r0) s[nf][0] = -1e30f;
                    if (c0 + 1 > r0) s[nf][1] = -1e30f;
                    if (c0     > r1) s[nf][2] = -1e30f;
                    if (c0 + 1 > r1) s[nf][3] = -1e30f;
                }
            }

            // ---- online softmax ----
            float mx0 = -1e30f, mx1 = -1e30f;
#pragma unroll
            for (int nf = 0; nf < 8; nf++) {
                mx0 = fmaxf(mx0, fmaxf(s[nf][0], s[nf][1]));
                mx1 = fmaxf(mx1, fmaxf(s[nf][2], s[nf][3]));
            }
            mx0 = fmaxf(mx0, __shfl_xor_sync(0xffffffffu, mx0, 1));
            mx0 = fmaxf(mx0, __shfl_xor_sync(0xffffffffu, mx0, 2));
            mx1 = fmaxf(mx1, __shfl_xor_sync(0xffffffffu, mx1, 1));
            mx1 = fmaxf(mx1, __shfl_xor_sync(0xffffffffu, mx1, 2));
            const float mn0 = fmaxf(m0, mx0), mn1 = fmaxf(m1, mx1);
            const float a0 = __expf(m0 - mn0), a1 = __expf(m1 - mn1);
            float sum0 = 0.f, sum1 = 0.f;
#pragma unroll
            for (int nf = 0; nf < 8; nf++) {
                s[nf][0] = __expf(s[nf][0] - mn0);
                s[nf][1] = __expf(s[nf][1] - mn0);
                s[nf][2] = __expf(s[nf][2] - mn1);
                s[nf][3] = __expf(s[nf][3] - mn1);
                sum0 += s[nf][0] + s[nf][1];
                sum1 += s[nf][2] + s[nf][3];
            }
            sum0 += __shfl_xor_sync(0xffffffffu, sum0, 1);
            sum0 += __shfl_xor_sync(0xffffffffu, sum0, 2);
            sum1 += __shfl_xor_sync(0xffffffffu, sum1, 1);
            sum1 += __shfl_xor_sync(0xffffffffu, sum1, 2);
            l0 = l0 * a0 + sum0;  l1 = l1 * a1 + sum1;
            m0 = mn0;             m1 = mn1;
#pragma unroll
            for (int nf = 0; nf < 16; nf++) {
                oacc[nf][0] *= a0; oacc[nf][1] *= a0;
                oacc[nf][2] *= a1; oacc[nf][3] *= a1;
            }

            // ---- pack P fragments ----
            uint32_t pah[4][4], pal[4][4];
#pragma unroll
            for (int j = 0; j < 4; j++) {
                pah[j][0] = pack2_hi(s[2*j][0],   s[2*j][1]);
                pah[j][1] = pack2_hi(s[2*j][2],   s[2*j][3]);
                pah[j][2] = pack2_hi(s[2*j+1][0], s[2*j+1][1]);
                pah[j][3] = pack2_hi(s[2*j+1][2], s[2*j+1][3]);
                pal[j][0] = pack2_lo(s[2*j][0],   s[2*j][1]);
                pal[j][1] = pack2_lo(s[2*j][2],   s[2*j][3]);
                pal[j][2] = pack2_lo(s[2*j+1][0], s[2*j+1][1]);
                pal[j][3] = pack2_lo(s[2*j+1][2], s[2*j+1][3]);
            }

            // ---- O += P @ V ----
#pragma unroll
            for (int j = 0; j < 4; j++) {
#pragma unroll
                for (int np = 0; np < 8; np++) {
                    const int nA = 2 * np, nB = 2 * np + 1;
                    uint32_t bhA0, bhA1, blA0, blA1, bhB0, bhB1, blB0, blB1;
                    LDSM_X2T(bhA0, bhA1, smem_u32(&Vh[(16 * j + vrow) * FLQ + nA * 8]));
                    LDSM_X2T(blA0, blA1, smem_u32(&Vl[(16 * j + vrow) * FLQ + nA * 8]));
                    LDSM_X2T(bhB0, bhB1, smem_u32(&Vh[(16 * j + vrow) * FLQ + nB * 8]));
                    LDSM_X2T(blB0, blB1, smem_u32(&Vl[(16 * j + vrow) * FLQ + nB * 8]));
                    MMA_BF16(oacc[nA], pah[j][0], pah[j][1], pah[j][2], pah[j][3], bhA0, bhA1);
                    MMA_BF16(oacc[nB], pah[j][0], pah[j][1], pah[j][2], pah[j][3], bhB0, bhB1);
                    MMA_BF16(oacc[nA], pah[j][0], pah[j][1], pah[j][2], pah[j][3], blA0, blA1);
                    MMA_BF16(oacc[nB], pah[j][0], pah[j][1], pah[j][2], pah[j][3], blB0, blB1);
                    MMA_BF16(oacc[nA], pal[j][0], pal[j][1], pal[j][2], pal[j][3], bhA0, bhA1);
                    MMA_BF16(oacc[nB], pal[j][0], pal[j][1], pal[j][2], pal[j][3], bhB0, bhB1);
                }
            }
        }

        // ---- normalize + store split planes ----
        const float inv0 = 1.f / l0, inv1 = 1.f / l1;
#pragma unroll
        for (int nf = 0; nf < 16; nf++) {
            const int col = h * HD + nf * 8 + t2;
            float v0 = oacc[nf][0] * inv0, v1 = oacc[nf][1] * inv0;
            float v2 = oacc[nf][2] * inv1, v3 = oacc[nf][3] * inv1;
            *(uint32_t*)&g_oh[(size_t)r0 * HID + col] = pack2_hi(v0, v1);
            *(uint32_t*)&g_ol[(size_t)r0 * HID + col] = pack2_lo(v0, v1);
            *(uint32_t*)&g_oh[(size_t)r1 * HID + col] = pack2_hi(v2, v3);
            *(uint32_t*)&g_ol[(size_t)r1 * HID + col] = pack2_lo(v2, v3);
        }
    }
}

// ---------------------------------------------------------------------------

extern "C" void kernel_launch(void* const* d_in, const int* in_sizes, int n_in,
                              void* d_out, int out_size)
{
    const float* x   = (const float*)d_in[0];
    /* d_in[1] attention_mask: exact causal triu(-inf), applied analytically */
    const int*   pos = (const int*)d_in[2];
    const float* wq  = (const float*)d_in[3];
    const float* bq  = (const float*)d_in[4];
    const float* wk  = (const float*)d_in[5];
    const float* bk  = (const float*)d_in[6];
    const float* wv  = (const float*)d_in[7];
    const float* bv  = (const float*)d_in[8];
    const float* wo  = (const float*)d_in[9];
    float*       out = (float*)d_out;

    bf16 *xh, *xl, *wqh, *wql, *wkh, *wkl, *wvh, *wvl, *woh, *wol;
    bf16 *qh, *ql, *kh, *kl;
    float *pq, *pk, *pv;
    cudaGetSymbolAddress((void**)&xh,  g_xh);  cudaGetSymbolAddress((void**)&xl,  g_xl);
    cudaGetSymbolAddress((void**)&wqh, g_wqh); cudaGetSymbolAddress((void**)&wql, g_wql);
    cudaGetSymbolAddress((void**)&wkh, g_wkh); cudaGetSymbolAddress((void**)&wkl, g_wkl);
    cudaGetSymbolAddress((void**)&wvh, g_wvh); cudaGetSymbolAddress((void**)&wvl, g_wvl);
    cudaGetSymbolAddress((void**)&woh, g_woh); cudaGetSymbolAddress((void**)&wol, g_wol);
    cudaGetSymbolAddress((void**)&qh,  g_qh);  cudaGetSymbolAddress((void**)&ql,  g_ql);
    cudaGetSymbolAddress((void**)&kh,  g_kh);  cudaGetSymbolAddress((void**)&kl,  g_kl);
    cudaGetSymbolAddress((void**)&pq,  g_pq);
    cudaGetSymbolAddress((void**)&pk,  g_pk);
    cudaGetSymbolAddress((void**)&pv,  g_pv);

    bf16 *vh, *vl;
    cudaGetSymbolAddress((void**)&vh, g_vh);
    cudaGetSymbolAddress((void**)&vl, g_vl);

    cudaFuncSetAttribute(qkv_gemm_sk, cudaFuncAttributeMaxDynamicSharedMemorySize, GSMEM);
    cudaFuncSetAttribute(o_gemm,      cudaFuncAttributeMaxDynamicSharedMemorySize, GSMEM);
    cudaFuncSetAttribute(flash_sp,    cudaFuncAttributeMaxDynamicSharedMemorySize, FSMEM);

    // one-shot splits (memory bound)
    split_f32<<<(S_LEN * HID / 4 + 255) / 256, 256>>>(x,  xh,  xl,  S_LEN * HID / 4);
    split_f32<<<(HID * HID / 4 + 255) / 256, 256>>>(wq, wqh, wql, HID * HID / 4);
    split_f32<<<(KVH * HID / 4 + 255) / 256, 256>>>(wk, wkh, wkl, KVH * HID / 4);
    split_f32<<<(KVH * HID / 4 + 255) / 256, 256>>>(wv, wvh, wvl, KVH * HID / 4);
    split_f32<<<(HID * HID / 4 + 255) / 256, 256>>>(wo, woh, wol, HID * HID / 4);

    // fused QKV projection, split-K x2 (768 uniform CTAs -> no half-empty wave)
    qkv_gemm_sk<<<dim3(48, 16), 256, GSMEM>>>();

    // combine split-K partials (+bias) into bf16 split planes
    combine_sp<<<(S_LEN * HID / 4 + 255) / 256, 256>>>(
        pq, pq + (size_t)S_LEN * HID, bq, qh, ql, HID, S_LEN * HID / 4);
    combine_sp<<<(S_LEN * KVH / 4 + 255) / 256, 256>>>(
        pk, pk + (size_t)S_LEN * KVH, bk, kh, kl, KVH, S_LEN * KVH / 4);
    combine_sp<<<(S_LEN * KVH / 4 + 255) / 256, 256>>>(
        pv, pv + (size_t)S_LEN * KVH, bv, vh, vl, KVH, S_LEN * KVH / 4);

    // RoPE on split planes
    {
        int totq = S_LEN * NH * 64;
        rope_sp<<<(totq + 255) / 256, 256>>>(qh, ql, pos, NH, HID, totq);
        int totk = S_LEN * NKV * 64;
        rope_sp<<<(totk + 255) / 256, 256>>>(kh, kl, pos, NKV, KVH, totk);
    }

    // flash attention (qt-paired, 128 uniform blocks)
    flash_sp<<<dim3(8, NH), 256, FSMEM>>>();

    // output projection -> fp32
    o_gemm<<<dim3(HID / 128, S_LEN / 128), 256, GSMEM>>>(out);
}

// round 12
// speedup vs baseline: 3.2600x; 1.0944x over previous
#include <cuda_runtime.h>
#include <cuda_bf16.h>
#include <math.h>
#include <stdint.h>

#define S_LEN 2048
#define HID   2048
#define NH    16
#define NKV   4
#define HD    128
#define KVH   512

typedef __nv_bfloat16 bf16;

// ------------------- split-plane scratch (bf16 hi/lo) -------------------
__device__ bf16 g_xh[S_LEN * HID], g_xl[S_LEN * HID];
__device__ bf16 g_wqh[HID * HID],  g_wql[HID * HID];
__device__ bf16 g_wkh[KVH * HID],  g_wkl[KVH * HID];
__device__ bf16 g_wvh[KVH * HID],  g_wvl[KVH * HID];
__device__ bf16 g_woh[HID * HID],  g_wol[HID * HID];
__device__ bf16 g_qh[S_LEN * HID], g_ql[S_LEN * HID];
__device__ bf16 g_kh[S_LEN * KVH], g_kl[S_LEN * KVH];
__device__ bf16 g_vh[S_LEN * KVH], g_vl[S_LEN * KVH];
__device__ bf16 g_oh[S_LEN * HID], g_ol[S_LEN * HID];

// split-K fp32 partials (2 halves each)
__device__ float g_pq[2 * S_LEN * HID];
__device__ float g_pk[2 * S_LEN * KVH];
__device__ float g_pv[2 * S_LEN * KVH];

__device__ __forceinline__ uint32_t smem_u32(const void* p) {
    return (uint32_t)__cvta_generic_to_shared(p);
}

#define MMA_BF16(c, a0, a1, a2, a3, b0, b1)                                 \
    asm("mma.sync.aligned.m16n8k16.row.col.f32.bf16.bf16.f32 "              \
        "{%0,%1,%2,%3},{%4,%5,%6,%7},{%8,%9},{%0,%1,%2,%3};"                \
        : "+f"(c[0]), "+f"(c[1]), "+f"(c[2]), "+f"(c[3])                    \
        : "r"(a0), "r"(a1), "r"(a2), "r"(a3), "r"(b0), "r"(b1))

#define LDSM_X4(r0, r1, r2, r3, addr)                                       \
    asm("ldmatrix.sync.aligned.m8n8.x4.shared.b16 {%0,%1,%2,%3},[%4];"      \
        : "=r"(r0), "=r"(r1), "=r"(r2), "=r"(r3) : "r"(addr))

#define LDSM_X4T(r0, r1, r2, r3, addr)                                      \
    asm("ldmatrix.sync.aligned.m8n8.x4.trans.shared.b16 {%0,%1,%2,%3},[%4];"\
        : "=r"(r0), "=r"(r1), "=r"(r2), "=r"(r3) : "r"(addr))

#define CP_ASYNC16(dst, src)                                                \
    asm volatile("cp.async.cg.shared.global [%0],[%1],16;"                  \
                 :: "r"(dst), "l"(src))
#define CP_COMMIT  asm volatile("cp.async.commit_group;" ::: "memory")
#define CP_WAIT(n) asm volatile("cp.async.wait_group %0;" :: "n"(n) : "memory")

__device__ __forceinline__ uint32_t pack2_hi(float x, float y) {
    __nv_bfloat162 t;
    t.x = __float2bfloat16(x); t.y = __float2bfloat16(y);
    return *(uint32_t*)&t;
}
__device__ __forceinline__ uint32_t pack2_lo(float x, float y) {
    __nv_bfloat162 t;
    t.x = __float2bfloat16(x - __bfloat162float(__float2bfloat16(x)));
    t.y = __float2bfloat16(y - __bfloat162float(__float2bfloat16(y)));
    return *(uint32_t*)&t;
}

// ---------------------------------------------------------------------------
// Fused one-shot split of x + 4 weight matrices (single launch)
// ---------------------------------------------------------------------------
#define N_X   (S_LEN * HID / 4)
#define N_WQ  (HID * HID / 4)
#define N_WKV (KVH * HID / 4)
#define N_SPLIT_TOT (N_X + 2 * N_WQ + 2 * N_WKV)

__global__ void split_all(const float* __restrict__ x,
                          const float* __restrict__ wq,
                          const float* __restrict__ wk,
                          const float* __restrict__ wv,
                          const float* __restrict__ wo)
{
    int i = blockIdx.x * blockDim.x + threadIdx.x;
    if (i >= N_SPLIT_TOT) return;
    const float* src; bf16 *hi, *lo; int local = i;
    if (local < N_X)                        { src = x;  hi = g_xh;  lo = g_xl;  }
    else if ((local -= N_X)   < N_WQ)       { src = wq; hi = g_wqh; lo = g_wql; }
    else if ((local -= N_WQ)  < N_WKV)      { src = wk; hi = g_wkh; lo = g_wkl; }
    else if ((local -= N_WKV) < N_WKV)      { src = wv; hi = g_wvh; lo = g_wvl; }
    else { local -= N_WKV;                    src = wo; hi = g_woh; lo = g_wol; }

    float4 v = ((const float4*)src)[local];
    ((uint32_t*)hi)[local * 2]     = pack2_hi(v.x, v.y);
    ((uint32_t*)hi)[local * 2 + 1] = pack2_hi(v.z, v.w);
    ((uint32_t*)lo)[local * 2]     = pack2_lo(v.x, v.y);
    ((uint32_t*)lo)[local * 2 + 1] = pack2_lo(v.z, v.w);
}

// ---------------------------------------------------------------------------
// Fused split-K combine + bias + RoPE (Q,K) / combine + bias (V) -> planes.
// Thread handles the (i, i+64) pair of one (s, head).
// ---------------------------------------------------------------------------
#define NQE (S_LEN * NH * 64)
#define NKE (S_LEN * NKV * 64)
#define N_CR_TOT (NQE + 2 * NKE)

__global__ void combine_rope(const int* __restrict__ pos_ids,
                             const float* __restrict__ bq,
                             const float* __restrict__ bk,
                             const float* __restrict__ bv)
{
    int idx = blockIdx.x * blockDim.x + threadIdx.x;
    if (idx >= N_CR_TOT) return;

    const float *p0, *p1, *bias; bf16 *hi, *lo;
    int stride, s, h, i; bool rot;
    if (idx < NQE) {
        i = idx & 63; h = (idx >> 6) & 15; s = idx >> 10;
        p0 = g_pq; p1 = g_pq + (size_t)S_LEN * HID; bias = bq;
        hi = g_qh; lo = g_ql; stride = HID; rot = true;
    } else if (idx < NQE + NKE) {
        int r = idx - NQE;
        i = r & 63; h = (r >> 6) & 3; s = r >> 8;
        p0 = g_pk; p1 = g_pk + (size_t)S_LEN * KVH; bias = bk;
        hi = g_kh; lo = g_kl; stride = KVH; rot = true;
    } else {
        int r = idx - NQE - NKE;
        i = r & 63; h = (r >> 6) & 3; s = r >> 8;
        p0 = g_pv; p1 = g_pv + (size_t)S_LEN * KVH; bias = bv;
        hi = g_vh; lo = g_vl; stride = KVH; rot = false;
    }

    const size_t base = (size_t)s * stride + h * HD;
    float v0 = p0[base + i]      + p1[base + i]      + bias[h * HD + i];
    float v1 = p0[base + i + 64] + p1[base + i + 64] + bias[h * HD + i + 64];

    if (rot) {
        float pos = (float)pos_ids[s];
        float inv = expf(-(float)(2 * i) * (1.0f / 128.0f) * 9.210340371976184f);
        float ang = pos * inv;
        float c, sn;
        sincosf(ang, &sn, &c);
        float y0 = v0 * c - v1 * sn;
        float y1 = v1 * c + v0 * sn;
        v0 = y0; v1 = y1;
    }

    bf16 h0 = __float2bfloat16(v0);
    bf16 h1 = __float2bfloat16(v1);
    hi[base + i]      = h0;
    lo[base + i]      = __float2bfloat16(v0 - __bfloat162float(h0));
    hi[base + i + 64] = h1;
    lo[base + i + 64] = __float2bfloat16(v1 - __bfloat162float(h1));
}

// ---------------------------------------------------------------------------
// GEMM core: C[M,N] = A @ B^T over K range. bf16 planes in, 3-term MMA,
// term-major, B loads via paired LDSM_X4. 128x128 tile, BK=32, double-buffered.
// ---------------------------------------------------------------------------
#define PLANE_B 10240          // 128 rows * 40 elems * 2B
#define BUF_B   40960          // 4 planes
#define GSMEM   81920          // 2 buffers

__device__ __forceinline__ void gemm_prefetch(
    uint32_t s_base, int buf,
    const bf16* __restrict__ Ahg, const bf16* __restrict__ Alg,
    const bf16* __restrict__ Bhg, const bf16* __restrict__ Blg,
    int bm, int bn, int K, int k0, int tid)
{
#pragma unroll
    for (int j = 0; j < 8; j++) {
        const int plane = j >> 1;
        const int t = tid * 2 + (j & 1);     // 0..511
        const int r = t >> 2, c8 = t & 3;
        const bf16* src = (plane == 0) ? Ahg : (plane == 1) ? Alg
                        : (plane == 2) ? Bhg : Blg;
        const int rowbase = (plane < 2) ? bm : bn;
        uint32_t dst = s_base + (uint32_t)buf * BUF_B + (uint32_t)plane * PLANE_B
                     + (uint32_t)(r * 40 + c8 * 8) * 2;
        CP_ASYNC16(dst, src + (size_t)(rowbase + r) * K + k0 + c8 * 8);
    }
}

__device__ __forceinline__ void gemm_core(
    const bf16* __restrict__ Ahg, const bf16* __restrict__ Alg,
    const bf16* __restrict__ Bhg, const bf16* __restrict__ Blg,
    float* __restrict__ Cf,
    int bm, int bn, int N, int K, int kstart, int klen)
{
    extern __shared__ bf16 smbuf[];
    const uint32_t s_base = smem_u32(smbuf);
    const int tid  = threadIdx.x, warp = tid >> 5, lane = tid & 31;
    const int wm   = (warp & 1) * 64, wn = (warp >> 1) * 32;
    const int g    = lane >> 2, t2 = (lane & 3) * 2;
    const int arow = (lane & 7) + ((lane & 8) ? 8 : 0);
    const int brow4 = (lane & 7) + ((lane & 16) ? 8 : 0);

    float acc[4][4][4];
#pragma unroll
    for (int mi = 0; mi < 4; mi++)
#pragma unroll
        for (int ni = 0; ni < 4; ni++)
#pragma unroll
            for (int q = 0; q < 4; q++) acc[mi][ni][q] = 0.f;

    const int nchunk = klen >> 5;
    gemm_prefetch(s_base, 0, Ahg, Alg, Bhg, Blg, bm, bn, K, kstart, tid);
    CP_COMMIT;

    for (int c = 0; c < nchunk; c++) {
        if (c + 1 < nchunk) {
            gemm_prefetch(s_base, (c + 1) & 1, Ahg, Alg, Bhg, Blg,
                          bm, bn, K, kstart + ((c + 1) << 5), tid);
            CP_COMMIT;
            CP_WAIT(1);
        } else {
            CP_WAIT(0);
        }
        __syncthreads();

        const uint32_t bufb = s_base + (uint32_t)(c & 1) * BUF_B;
        const uint32_t aAh = bufb, aAl = bufb + PLANE_B;
        const uint32_t aBh = bufb + 2 * PLANE_B, aBl = bufb + 3 * PLANE_B;

#pragma unroll
        for (int kt = 0; kt < 32; kt += 16) {
            const int acol = kt + ((lane & 16) ? 8 : 0);
            uint32_t ah[4][4], al[4][4];
#pragma unroll
            for (int mi = 0; mi < 4; mi++) {
                const uint32_t off = (uint32_t)((wm + mi * 16 + arow) * 40 + acol) * 2;
                LDSM_X4(ah[mi][0], ah[mi][1], ah[mi][2], ah[mi][3], aAh + off);
                LDSM_X4(al[mi][0], al[mi][1], al[mi][2], al[mi][3], aAl + off);
            }
            const int bcol = kt + ((lane & 8) ? 8 : 0);
#pragma unroll
            for (int np = 0; np < 2; np++) {
                const uint32_t boff = (uint32_t)((wn + np * 16 + brow4) * 40 + bcol) * 2;
                uint32_t bh[4], bl[4];
                LDSM_X4(bh[0], bh[1], bh[2], bh[3], aBh + boff);
                LDSM_X4(bl[0], bl[1], bl[2], bl[3], aBl + boff);
                const int nA = 2 * np, nB = 2 * np + 1;
#pragma unroll
                for (int mi = 0; mi < 4; mi++)
                    MMA_BF16(acc[mi][nA], ah[mi][0], ah[mi][1], ah[mi][2], ah[mi][3], bh[0], bh[1]);
#pragma unroll
                for (int mi = 0; mi < 4; mi++)
                    MMA_BF16(acc[mi][nB], ah[mi][0], ah[mi][1], ah[mi][2], ah[mi][3], bh[2], bh[3]);
#pragma unroll
                for (int mi = 0; mi < 4; mi++)
                    MMA_BF16(acc[mi][nA], ah[mi][0], ah[mi][1], ah[mi][2], ah[mi][3], bl[0], bl[1]);
#pragma unroll
                for (int mi = 0; mi < 4; mi++)
                    MMA_BF16(acc[mi][nB], ah[mi][0], ah[mi][1], ah[mi][2], ah[mi][3], bl[2], bl[3]);
#pragma unroll
                for (int mi = 0; mi < 4; mi++)
                    MMA_BF16(acc[mi][nA], al[mi][0], al[mi][1], al[mi][2], al[mi][3], bh[0], bh[1]);
#pragma unroll
                for (int mi = 0; mi < 4; mi++)
                    MMA_BF16(acc[mi][nB], al[mi][0], al[mi][1], al[mi][2], al[mi][3], bh[2], bh[3]);
            }
        }
        __syncthreads();
    }

#pragma unroll
    for (int mi = 0; mi < 4; mi++) {
#pragma unroll
        for (int ni = 0; ni < 4; ni++) {
            const int row = bm + wm + mi * 16 + g;
            const int col = bn + wn + ni * 8 + t2;
            float2 w0; w0.x = acc[mi][ni][0]; w0.y = acc[mi][ni][1];
            float2 w1; w1.x = acc[mi][ni][2]; w1.y = acc[mi][ni][3];
            *(float2*)&Cf[(size_t)row * N + col]       = w0;
            *(float2*)&Cf[(size_t)(row + 8) * N + col] = w1;
        }
    }
}

// QKV split-K: bx = tilecol*2 + ks. tilecol 0..15 -> Q, 16..19 -> K, 20..23 -> V
__global__ __launch_bounds__(256) void qkv_gemm_sk()
{
    const int bx = blockIdx.x;            // 0..47
    const int tc = bx >> 1, ks = bx & 1;
    const int bm = blockIdx.y * 128;
    const int kstart = ks * (HID / 2);
    if (tc < 16)
        gemm_core(g_xh, g_xl, g_wqh, g_wql,
                  g_pq + (size_t)ks * S_LEN * HID,
                  bm, tc * 128, HID, HID, kstart, HID / 2);
    else if (tc < 20)
        gemm_core(g_xh, g_xl, g_wkh, g_wkl,
                  g_pk + (size_t)ks * S_LEN * KVH,
                  bm, (tc - 16) * 128, KVH, HID, kstart, HID / 2);
    else
        gemm_core(g_xh, g_xl, g_wvh, g_wvl,
                  g_pv + (size_t)ks * S_LEN * KVH,
                  bm, (tc - 20) * 128, KVH, HID, kstart, HID / 2);
}

__global__ __launch_bounds__(256) void o_gemm(float* __restrict__ out)
{
    gemm_core(g_oh, g_ol, g_woh, g_wol, out,
              blockIdx.y * 128, blockIdx.x * 128, HID, HID, 0, HID);
}

// ---------------------------------------------------------------------------
// Flash attention, warp-mma bf16 3-term, KV double-buffered, qt-paired,
// paired LDSM_X4 K/V loads + zero-work skips near the diagonal.
// ---------------------------------------------------------------------------
#define FLQ 136
#define KVSET (4 * 64 * FLQ)
#define FSMEM ((2 * 128 * FLQ + 2 * KVSET) * 2)       // 208896 bytes

__device__ __forceinline__ void flash_kv_load(
    bf16* kvbase, int kvh, int j0, int tid)
{
#pragma unroll
    for (int j = 0; j < 16; j++) {
        const int plane = j >> 2;
        const int tt = tid * 4 + (j & 3);
        const int r = tt >> 4, c16 = tt & 15;
        const bf16* src;
        if (plane == 0)      src = g_kh;
        else if (plane == 1) src = g_kl;
        else if (plane == 2) src = g_vh;
        else                 src = g_vl;
        src += (size_t)(j0 + r) * KVH + kvh * HD + c16 * 8;
        uint32_t dst = smem_u32(kvbase + plane * 64 * FLQ + r * FLQ + c16 * 8);
        CP_ASYNC16(dst, src);
    }
}

__global__ __launch_bounds__(256) void flash_sp()
{
    extern __shared__ bf16 sm[];
    bf16* Qh = sm;
    bf16* Ql = Qh + 128 * FLQ;
    bf16* KV = Ql + 128 * FLQ;

    const int h   = blockIdx.y;
    const int kvh = h >> 2;
    const int tid = threadIdx.x, warp = tid >> 5, lane = tid & 31;
    const int g   = lane >> 2, t2 = (lane & 3) * 2;
    const float scale = 0.08838834764831845f;
    const int mrow = warp * 16;
    const int arow = (lane & 7) + ((lane & 8) ? 8 : 0);
    const int brow4 = (lane & 7) + ((lane & 16) ? 8 : 0);
    const int vrow = lane & 15;
    const int vsel = (lane & 16) ? 1 : 0;

    for (int pass = 0; pass < 2; pass++) {
        const int qt = pass == 0 ? (15 - (int)blockIdx.x) : (int)blockIdx.x;
        const int q0 = qt * 128;

        __syncthreads();   // prior pass fully done with Qh/Ql/KV

        // Q tile via cp.async (2 planes, 128x128)
#pragma unroll
        for (int j = 0; j < 16; j++) {
            const int plane = j >> 3;
            const int t = tid * 8 + (j & 7);
            const int r = t >> 4, c16 = t & 15;
            const bf16* src = (plane ? g_ql : g_qh) + (size_t)(q0 + r) * HID + h * HD + c16 * 8;
            uint32_t dst = smem_u32((plane ? Ql : Qh) + r * FLQ + c16 * 8);
            CP_ASYNC16(dst, src);
        }
        CP_COMMIT;

        float m0 = -1e30f, m1 = -1e30f, l0 = 0.f, l1 = 0.f;
        float oacc[16][4];
#pragma unroll
        for (int nf = 0; nf < 16; nf++)
#pragma unroll
            for (int q = 0; q < 4; q++) oacc[nf][q] = 0.f;

        const int r0 = q0 + mrow + g, r1 = r0 + 8;
        const int wmax = q0 + mrow + 15;
        const int ntiles = 2 * qt + 2;

        flash_kv_load(KV, kvh, 0, tid);
        CP_COMMIT;

        for (int t = 0; t < ntiles; t++) {
            const int j0 = t * 64;
            __syncthreads();
            if (t + 1 < ntiles) {
                flash_kv_load(KV + ((t + 1) & 1) * KVSET, kvh, (t + 1) * 64, tid);
                CP_COMMIT;
                CP_WAIT(1);
            } else {
                CP_WAIT(0);
            }
            __syncthreads();
            if (j0 > wmax) continue;

            bf16* Kh = KV + (t & 1) * KVSET;
            bf16* Kl = Kh + 64 * FLQ;
            bf16* Vh = Kl + 64 * FLQ;
            bf16* Vl = Vh + 64 * FLQ;

            // ---- S = Q K^T ----
            float s[8][4];
#pragma unroll
            for (int nf = 0; nf < 8; nf++)
#pragma unroll
                for (int q = 0; q < 4; q++) s[nf][q] = 0.f;

#pragma unroll
            for (int kt = 0; kt < 128; kt += 16) {
                const int acol = kt + ((lane & 16) ? 8 : 0);
                uint32_t qh[4], ql[4];
                LDSM_X4(qh[0], qh[1], qh[2], qh[3], smem_u32(&Qh[(mrow + arow) * FLQ + acol]));
                LDSM_X4(ql[0], ql[1], ql[2], ql[3], smem_u32(&Ql[(mrow + arow) * FLQ + acol]));
                const int bcol = kt + ((lane & 8) ? 8 : 0);
#pragma unroll
                for (int np = 0; np < 4; np++) {
                    if (j0 + np * 16 > wmax) continue;   // fully-masked cols
                    const int nA = 2 * np, nB = 2 * np + 1;
                    uint32_t kh[4], kl[4];
                    LDSM_X4(kh[0], kh[1], kh[2], kh[3],
                            smem_u32(&Kh[(np * 16 + brow4) * FLQ + bcol]));
                    LDSM_X4(kl[0], kl[1], kl[2], kl[3],
                            smem_u32(&Kl[(np * 16 + brow4) * FLQ + bcol]));
                    MMA_BF16(s[nA], qh[0], qh[1], qh[2], qh[3], kh[0], kh[1]);
                    MMA_BF16(s[nB], qh[0], qh[1], qh[2], qh[3], kh[2], kh[3]);
                    MMA_BF16(s[nA], qh[0], qh[1], qh[2], qh[3], kl[0], kl[1]);
                    MMA_BF16(s[nB], qh[0], qh[1], qh[2], qh[3], kl[2], kl[3]);
                    MMA_BF16(s[nA], ql[0], ql[1], ql[2], ql[3], kh[0], kh[1]);
                    MMA_BF16(s[nB], ql[0], ql[1], ql[2], ql[3], kh[2], kh[3]);
                }
            }

#pragma unroll
            for (int nf = 0; nf < 8; nf++)
#pragma unroll
                for (int q = 0; q < 4; q++) s[nf][q] *= scale;

            if (j0 + 63 > r0) {
#pragma unroll
                for (int nf = 0; nf < 8; nf++) {
                    const int c0 = j0 + nf * 8 + t2;
                    if (c0     > r0) s[nf][0] = -1e30f;
                    if (c0 + 1 > r0) s[nf][1] = -1e30f;
                    if (c0     > r1) s[nf][2] = -1e30f;
                    if (c0 + 1 > r1) s[nf][3] = -1e30f;
                }
            }

            // ---- online softmax ----
            float mx0 = -1e30f, mx1 = -1e30f;
#pragma unroll
            for (int nf = 0; nf < 8; nf++) {
                mx0 = fmaxf(mx0, fmaxf(s[nf][0], s[nf][1]));
                mx1 = fmaxf(mx1, fmaxf(s[nf][2], s[nf][3]));
            }
            mx0 = fmaxf(mx0, __shfl_xor_sync(0xffffffffu, mx0, 1));
            mx0 = fmaxf(mx0, __shfl_xor_sync(0xffffffffu, mx0, 2));
            mx1 = fmaxf(mx1, __shfl_xor_sync(0xffffffffu, mx1, 1));
            mx1 = fmaxf(mx1, __shfl_xor_sync(0xffffffffu, mx1, 2));
            const float mn0 = fmaxf(m0, mx0), mn1 = fmaxf(m1, mx1);
            const float a0 = __expf(m0 - mn0), a1 = __expf(m1 - mn1);
            float sum0 = 0.f, sum1 = 0.f;
#pragma unroll
            for (int nf = 0; nf < 8; nf++) {
                s[nf][0] = __expf(s[nf][0] - mn0);
                s[nf][1] = __expf(s[nf][1] - mn0);
                s[nf][2] = __expf(s[nf][2] - mn1);
                s[nf][3] = __expf(s[nf][3] - mn1);
                sum0 += s[nf][0] + s[nf][1];
                sum1 += s[nf][2] + s[nf][3];
            }
            sum0 += __shfl_xor_sync(0xffffffffu, sum0, 1);
            sum0 += __shfl_xor_sync(0xffffffffu, sum0, 2);
            sum1 += __shfl_xor_sync(0xffffffffu, sum1, 1);
            sum1 += __shfl_xor_sync(0xffffffffu, sum1, 2);
            l0 = l0 * a0 + sum0;  l1 = l1 * a1 + sum1;
            m0 = mn0;             m1 = mn1;
#pragma unroll
            for (int nf = 0; nf < 16; nf++) {
                oacc[nf][0] *= a0; oacc[nf][1] *= a0;
                oacc[nf][2] *= a1; oacc[nf][3] *= a1;
            }

            // ---- pack P fragments ----
            uint32_t pah[4][4], pal[4][4];
#pragma unroll
            for (int j = 0; j < 4; j++) {
                pah[j][0] = pack2_hi(s[2*j][0],   s[2*j][1]);
                pah[j][1] = pack2_hi(s[2*j][2],   s[2*j][3]);
                pah[j][2] = pack2_hi(s[2*j+1][0], s[2*j+1][1]);
                pah[j][3] = pack2_hi(s[2*j+1][2], s[2*j+1][3]);
                pal[j][0] = pack2_lo(s[2*j][0],   s[2*j][1]);
                pal[j][1] = pack2_lo(s[2*j][2],   s[2*j][3]);
                pal[j][2] = pack2_lo(s[2*j+1][0], s[2*j+1][1]);
                pal[j][3] = pack2_lo(s[2*j+1][2], s[2*j+1][3]);
            }

            // ---- O += P @ V ----
#pragma unroll
            for (int j = 0; j < 4; j++) {
                if (j0 + 16 * j > wmax) continue;   // P columns all zero
#pragma unroll
                for (int np = 0; np < 8; np++) {
                    const int nA = 2 * np, nB = 2 * np + 1;
                    const int vcol = (nA + vsel) * 8;
                    uint32_t vh[4], vl[4];
                    LDSM_X4T(vh[0], vh[1], vh[2], vh[3],
                             smem_u32(&Vh[(16 * j + vrow) * FLQ + vcol]));
                    LDSM_X4T(vl[0], vl[1], vl[2], vl[3],
                             smem_u32(&Vl[(16 * j + vrow) * FLQ + vcol]));
                    MMA_BF16(oacc[nA], pah[j][0], pah[j][1], pah[j][2], pah[j][3], vh[0], vh[1]);
                    MMA_BF16(oacc[nB], pah[j][0], pah[j][1], pah[j][2], pah[j][3], vh[2], vh[3]);
                    MMA_BF16(oacc[nA], pah[j][0], pah[j][1], pah[j][2], pah[j][3], vl[0], vl[1]);
                    MMA_BF16(oacc[nB], pah[j][0], pah[j][1], pah[j][2], pah[j][3], vl[2], vl[3]);
                    MMA_BF16(oacc[nA], pal[j][0], pal[j][1], pal[j][2], pal[j][3], vh[0], vh[1]);
                    MMA_BF16(oacc[nB], pal[j][0], pal[j][1], pal[j][2], pal[j][3], vh[2], vh[3]);
                }
            }
        }

        // ---- normalize + store split planes ----
        const float inv0 = 1.f / l0, inv1 = 1.f / l1;
#pragma unroll
        for (int nf = 0; nf < 16; nf++) {
            const int col = h * HD + nf * 8 + t2;
            float v0 = oacc[nf][0] * inv0, v1 = oacc[nf][1] * inv0;
            float v2 = oacc[nf][2] * inv1, v3 = oacc[nf][3] * inv1;
            *(uint32_t*)&g_oh[(size_t)r0 * HID + col] = pack2_hi(v0, v1);
            *(uint32_t*)&g_ol[(size_t)r0 * HID + col] = pack2_lo(v0, v1);
            *(uint32_t*)&g_oh[(size_t)r1 * HID + col] = pack2_hi(v2, v3);
            *(uint32_t*)&g_ol[(size_t)r1 * HID + col] = pack2_lo(v2, v3);
        }
    }
}

// ---------------------------------------------------------------------------

extern "C" void kernel_launch(void* const* d_in, const int* in_sizes, int n_in,
                              void* d_out, int out_size)
{
    const float* x   = (const float*)d_in[0];
    /* d_in[1] attention_mask: exact causal triu(-inf), applied analytically */
    const int*   pos = (const int*)d_in[2];
    const float* wq  = (const float*)d_in[3];
    const float* bq  = (const float*)d_in[4];
    const float* wk  = (const float*)d_in[5];
    const float* bk  = (const float*)d_in[6];
    const float* wv  = (const float*)d_in[7];
    const float* bv  = (const float*)d_in[8];
    const float* wo  = (const float*)d_in[9];
    float*       out = (float*)d_out;

    cudaFuncSetAttribute(qkv_gemm_sk, cudaFuncAttributeMaxDynamicSharedMemorySize, GSMEM);
    cudaFuncSetAttribute(o_gemm,      cudaFuncAttributeMaxDynamicSharedMemorySize, GSMEM);
    cudaFuncSetAttribute(flash_sp,    cudaFuncAttributeMaxDynamicSharedMemorySize, FSMEM);

    // one-shot splits (single launch)
    split_all<<<(N_SPLIT_TOT + 255) / 256, 256>>>(x, wq, wk, wv, wo);

    // fused QKV projection, split-K x2 (768 uniform CTAs)
    qkv_gemm_sk<<<dim3(48, 16), 256, GSMEM>>>();

    // combine split-K partials + bias + RoPE -> bf16 planes (single launch)
    combine_rope<<<(N_CR_TOT + 255) / 256, 256>>>(pos, bq, bk, bv);

    // flash attention (qt-paired, 128 uniform blocks)
    flash_sp<<<dim3(8, NH), 256, FSMEM>>>();

    // output projection -> fp32
    o_gemm<<<dim3(HID / 128, S_LEN / 128), 256, GSMEM>>>(out);
}